// round 12
// baseline (speedup 1.0000x reference)
#include <cuda_runtime.h>
#include <cstdint>
#include <cstddef>

// Problem dims
#define NB 8
#define C 128
#define HH 36
#define WW 36
#define P (HH*WW)          // 1296 query tokens
#define HV 34
#define WV 34
#define D (HV*WV)          // 1156 key/value tokens
#define KC (C*9)           // 1152 im2col K

// -------- scratch (static device memory; no allocation APIs) --------
__device__ uint32_t g_xa[(size_t)NB*2*C*P];   // rows 0..127: x, rows 128..255: a0
__device__ uint32_t g_q[(size_t)NB*C*P];
__device__ uint32_t g_k[(size_t)NB*C*D];
__device__ uint32_t g_v[(size_t)NB*C*D];
__device__ uint32_t g_sc[(size_t)NB*(size_t)P*D]; // exp(scores) tf32 bits
__device__ float    g_rs[(size_t)NB*P];           // row sums of exp
__device__ uint32_t g_h[(size_t)NB*C*P];
__device__ float    g_beff[C];
__device__ uint32_t g_wx[C*C];
__device__ uint32_t g_wq[C*KC];
__device__ uint32_t g_wk[C*KC];
__device__ uint32_t g_wv[C*KC];
__device__ uint32_t g_wh[C*3*C];
__device__ uint32_t g_wo[C*C];

// -------- tf32 helpers --------
__device__ __forceinline__ uint32_t f2tf32(float f) {
    uint32_t u;
    asm("cvt.rna.tf32.f32 %0, %1;" : "=r"(u) : "f"(f));
    return u;
}

__device__ __forceinline__ void mma_tf32(
    float& c0, float& c1, float& c2, float& c3,
    uint32_t a0, uint32_t a1, uint32_t a2, uint32_t a3,
    uint32_t b0, uint32_t b1)
{
    asm volatile(
        "mma.sync.aligned.m16n8k8.row.col.f32.tf32.tf32.f32 "
        "{%0,%1,%2,%3}, {%4,%5,%6,%7}, {%8,%9}, {%0,%1,%2,%3};"
        : "+f"(c0), "+f"(c1), "+f"(c2), "+f"(c3)
        : "r"(a0), "r"(a1), "r"(a2), "r"(a3), "r"(b0), "r"(b1));
}

// -------- weight pre-conversion (fp32 -> tf32 bits) --------
__global__ void preconv_k(const float* __restrict__ wx, const float* __restrict__ wq,
                          const float* __restrict__ wk, const float* __restrict__ wv,
                          const float* __restrict__ wh, const float* __restrict__ wo)
{
    int i = blockIdx.x * 256 + threadIdx.x;
    if (i < C*C)   { g_wx[i] = f2tf32(wx[i]); g_wo[i] = f2tf32(wo[i]); }
    if (i < C*3*C) g_wh[i] = f2tf32(wh[i]);
    if (i < C*KC)  {
        g_wq[i] = f2tf32(wq[i]);
        g_wk[i] = f2tf32(wk[i]);
        g_wv[i] = f2tf32(wv[i]);
    }
}

__global__ void zero_rs_k()
{
    int i = blockIdx.x * 256 + threadIdx.x;
    if (i < NB * P) g_rs[i] = 0.f;
}

// ============================================================
// qkv_mega: all three 3x3 conv GEMMs in ONE launch, tf32 MMA core.
// CTA tile 64(m) x 128(n), 128 threads = 4 warps, warp tile 32x64.
// ============================================================
__global__ void __launch_bounds__(128) qkv_mega_k(
    const uint32_t* __restrict__ xa,
    uint32_t* __restrict__ qo, uint32_t* __restrict__ ko, uint32_t* __restrict__ vo)
{
    __shared__ uint32_t As[2][16][72];
    __shared__ uint32_t Bs[2][16][136];

    const int bz = blockIdx.z;
    const int tile = blockIdx.x;
    bool qmode; int my, nx;
    if (tile < 22) { qmode = true;  my = tile / 11; nx = tile % 11; }
    else { int t2 = tile - 22; qmode = false; my = t2 / 10; nx = t2 % 10; }

    const uint32_t* A = qmode ? g_wq : ((my < 2) ? g_wk : g_wv);
    const int m0 = qmode ? my * 64 : (my & 1) * 64;
    const int Nn = qmode ? P : D;
    uint32_t* Cp = qmode ? (qo + (size_t)bz * C * P)
                         : ((my < 2) ? ko : vo) + (size_t)bz * C * D;
    const uint32_t* B = xa + (size_t)bz * 2 * C * P;
    const int n0 = nx * 128;
    const int ldc = Nn;

    const int tid = threadIdx.x;
    const int warp = tid >> 5, lane = tid & 31;
    const int g = lane >> 2, t = lane & 3;
    const int wm = warp & 1, wn = warp >> 1;
    const int m0w = wm * 32, n0w = wn * 64;

    const int ka = tid & 15;
    const int ma = tid >> 4;

    int p = n0 + tid;
    bool npred; int iy, ix;
    if (qmode) { npred = (p < P); if (p >= P) p = 0; iy = p / WW; ix = p % WW; }
    else       { npred = (p < D); if (p >= D) p = 0; iy = p / WV; ix = p % WV; }

    float acc[2][8][4];
    #pragma unroll
    for (int i = 0; i < 2; i++)
        #pragma unroll
        for (int j = 0; j < 8; j++)
            #pragma unroll
            for (int r = 0; r < 4; r++) acc[i][j][r] = 0.f;

    uint32_t ra[8], rb[16];

    auto loadAB = [&](int k0) {
        int ci_a = (k0 + ka) & 127, t_a = (k0 + ka) >> 7;
        #pragma unroll
        for (int i = 0; i < 8; i++) {
            int m = m0 + ma + 8 * i;
            ra[i] = A[(size_t)m * KC + ci_a * 9 + t_a];
        }
        int tt = k0 >> 7;
        int ky = tt / 3, kx = tt - ky * 3;
        int cb = k0 & 127;
        if (qmode) {
            int sy = iy + ky - 1, sx = ix + kx - 1;
            bool pr = npred && sy >= 0 && sy < HH && sx >= 0 && sx < WW;
            int rowb = sy * WW + sx;
            #pragma unroll
            for (int i = 0; i < 16; i++)
                rb[i] = pr ? B[(size_t)(cb + i) * P + rowb] : 0u;
        } else {
            int rowb = (iy + ky) * WW + (ix + kx);
            #pragma unroll
            for (int i = 0; i < 16; i++)
                rb[i] = npred ? B[(size_t)(cb + i) * P + rowb] : 0u;
        }
    };

    auto writeS = [&](int buf) {
        #pragma unroll
        for (int i = 0; i < 8; i++) As[buf][ka][ma + 8 * i] = ra[i];
        #pragma unroll
        for (int i = 0; i < 16; i++) Bs[buf][i][tid] = rb[i];
    };

    loadAB(0);
    writeS(0);
    __syncthreads();

    int buf = 0;
    for (int k0 = 0; k0 < KC; k0 += 16) {
        bool nxt = (k0 + 16) < KC;
        if (nxt) loadAB(k0 + 16);

        #pragma unroll
        for (int ks = 0; ks < 2; ks++) {
            int kb = ks * 8;
            uint32_t af[2][4], bf[8][2];
            #pragma unroll
            for (int mt = 0; mt < 2; mt++) {
                int mb = m0w + mt * 16 + g;
                af[mt][0] = As[buf][kb + t][mb];
                af[mt][1] = As[buf][kb + t][mb + 8];
                af[mt][2] = As[buf][kb + t + 4][mb];
                af[mt][3] = As[buf][kb + t + 4][mb + 8];
            }
            #pragma unroll
            for (int nt = 0; nt < 8; nt++) {
                int nb = n0w + nt * 8 + g;
                bf[nt][0] = Bs[buf][kb + t][nb];
                bf[nt][1] = Bs[buf][kb + t + 4][nb];
            }
            #pragma unroll
            for (int mt = 0; mt < 2; mt++)
                #pragma unroll
                for (int nt = 0; nt < 8; nt++)
                    mma_tf32(acc[mt][nt][0], acc[mt][nt][1], acc[mt][nt][2], acc[mt][nt][3],
                             af[mt][0], af[mt][1], af[mt][2], af[mt][3],
                             bf[nt][0], bf[nt][1]);
        }

        if (nxt) {
            writeS(buf ^ 1);
            __syncthreads();
            buf ^= 1;
        }
    }

    #pragma unroll
    for (int mt = 0; mt < 2; mt++) {
        int gm = m0 + m0w + mt * 16 + g;
        #pragma unroll
        for (int nt = 0; nt < 8; nt++) {
            int gn = n0 + n0w + nt * 8 + 2 * t;
            if (gn < Nn)     Cp[(size_t)gm * ldc + gn]           = f2tf32(acc[mt][nt][0]);
            if (gn + 1 < Nn) Cp[(size_t)gm * ldc + gn + 1]       = f2tf32(acc[mt][nt][1]);
            if (gn < Nn)     Cp[(size_t)(gm + 8) * ldc + gn]     = f2tf32(acc[mt][nt][2]);
            if (gn + 1 < Nn) Cp[(size_t)(gm + 8) * ldc + gn + 1] = f2tf32(acc[mt][nt][3]);
        }
    }
}

// ============================================================
// gemm128n: generic 64(m) x 128(n) tile GEMM, tf32 MMA core
// (inner pipeline identical to qkv_mega). C[128,N]=A[128,K]@B[K,N].
// A: tf32 bits, [M][K] row-major (lda), per-batch stride sA.
// BMODE: 0 = B plain [K][N] (ldb), 1 = B transposed [N][K] (ldb).
// BRAW: B already tf32 bits vs fp32 (cvt at load).
// EPI: 0 none, 1 +aux[m], 2 tanh(acc+aux[m]), 3 scale by 1/aux[n].
// OU32: write tf32 bits vs fp32.
// ============================================================
template<int BMODE, int EPI, bool BRAW, bool OU32>
__global__ void __launch_bounds__(128) gemm128n_k(
    const uint32_t* __restrict__ A, size_t sA, int lda,
    const void* __restrict__ Bv, size_t sB, int ldb,
    void* __restrict__ Cv, size_t sC, int ldc,
    int N, int K,
    const float* __restrict__ aux, size_t sAux)
{
    __shared__ uint32_t As[2][16][72];
    __shared__ uint32_t Bs[2][16][136];
    A += (size_t)blockIdx.z * sA;
    const uint32_t* B32 = (const uint32_t*)Bv + (BRAW ? (size_t)blockIdx.z * sB : 0);
    const float*    Bf  = (const float*)Bv    + (BRAW ? 0 : (size_t)blockIdx.z * sB);
    uint32_t* C32 = (uint32_t*)Cv + (size_t)blockIdx.z * sC;
    float*    Cf  = (float*)Cv    + (size_t)blockIdx.z * sC;
    const float* auxp = aux + (size_t)blockIdx.z * sAux;

    const int m0 = blockIdx.y * 64, n0 = blockIdx.x * 128;
    const int tid = threadIdx.x;
    const int warp = tid >> 5, lane = tid & 31;
    const int g = lane >> 2, t = lane & 3;
    const int wm = warp & 1, wn = warp >> 1;
    const int m0w = wm * 32, n0w = wn * 64;

    const int ka = tid & 15;
    const int ma = tid >> 4;

    float acc[2][8][4];
    #pragma unroll
    for (int i = 0; i < 2; i++)
        #pragma unroll
        for (int j = 0; j < 8; j++)
            #pragma unroll
            for (int r = 0; r < 4; r++) acc[i][j][r] = 0.f;

    uint32_t ra[8], rb[16];

    auto ldB = [&](int gk, int gn) -> uint32_t {
        if (BRAW) return B32[(size_t)(BMODE == 1 ? gn : gk) * ldb + (BMODE == 1 ? gk : gn)];
        else      return f2tf32(Bf[(size_t)(BMODE == 1 ? gn : gk) * ldb + (BMODE == 1 ? gk : gn)]);
    };

    auto loadAB = [&](int k0) {
        #pragma unroll
        for (int i = 0; i < 8; i++) {
            int gk = k0 + ka;
            int m = m0 + ma + 8 * i;
            ra[i] = (gk < K) ? A[(size_t)m * lda + gk] : 0u;
        }
        if (BMODE == 0) {
            int gn = n0 + tid;
            bool gok = (gn < N);
            #pragma unroll
            for (int i = 0; i < 16; i++) {
                int gk = k0 + i;
                rb[i] = (gok && gk < K) ? ldB(gk, gn) : 0u;
            }
        } else {
            int gk = k0 + ka;
            bool kok = (gk < K);
            #pragma unroll
            for (int i = 0; i < 16; i++) {
                int gn = n0 + ma + 8 * i;
                rb[i] = (kok && gn < N) ? ldB(gk, gn) : 0u;
            }
        }
    };

    auto writeS = [&](int buf) {
        #pragma unroll
        for (int i = 0; i < 8; i++) As[buf][ka][ma + 8 * i] = ra[i];
        if (BMODE == 0) {
            #pragma unroll
            for (int i = 0; i < 16; i++) Bs[buf][i][tid] = rb[i];
        } else {
            #pragma unroll
            for (int i = 0; i < 16; i++) Bs[buf][ka][ma + 8 * i] = rb[i];
        }
    };

    loadAB(0);
    writeS(0);
    __syncthreads();

    int buf = 0;
    for (int k0 = 0; k0 < K; k0 += 16) {
        bool nxt = (k0 + 16) < K;
        if (nxt) loadAB(k0 + 16);

        #pragma unroll
        for (int ks = 0; ks < 2; ks++) {
            int kb = ks * 8;
            uint32_t af[2][4], bf[8][2];
            #pragma unroll
            for (int mt = 0; mt < 2; mt++) {
                int mb = m0w + mt * 16 + g;
                af[mt][0] = As[buf][kb + t][mb];
                af[mt][1] = As[buf][kb + t][mb + 8];
                af[mt][2] = As[buf][kb + t + 4][mb];
                af[mt][3] = As[buf][kb + t + 4][mb + 8];
            }
            #pragma unroll
            for (int nt = 0; nt < 8; nt++) {
                int nb = n0w + nt * 8 + g;
                bf[nt][0] = Bs[buf][kb + t][nb];
                bf[nt][1] = Bs[buf][kb + t + 4][nb];
            }
            #pragma unroll
            for (int mt = 0; mt < 2; mt++)
                #pragma unroll
                for (int nt = 0; nt < 8; nt++)
                    mma_tf32(acc[mt][nt][0], acc[mt][nt][1], acc[mt][nt][2], acc[mt][nt][3],
                             af[mt][0], af[mt][1], af[mt][2], af[mt][3],
                             bf[nt][0], bf[nt][1]);
        }

        if (nxt) {
            writeS(buf ^ 1);
            __syncthreads();
            buf ^= 1;
        }
    }

    #pragma unroll
    for (int mt = 0; mt < 2; mt++) {
        int gm = m0 + m0w + mt * 16 + g;
        float bv0 = (EPI == 1 || EPI == 2) ? auxp[gm] : 0.f;
        float bv8 = (EPI == 1 || EPI == 2) ? auxp[gm + 8] : 0.f;
        #pragma unroll
        for (int nt = 0; nt < 8; nt++) {
            int gn = n0 + n0w + nt * 8 + 2 * t;
            float v0 = acc[mt][nt][0], v1 = acc[mt][nt][1];
            float v2 = acc[mt][nt][2], v3 = acc[mt][nt][3];
            if (EPI == 1) { v0 += bv0; v1 += bv0; v2 += bv8; v3 += bv8; }
            if (EPI == 2) {
                v0 = tanhf(v0 + bv0); v1 = tanhf(v1 + bv0);
                v2 = tanhf(v2 + bv8); v3 = tanhf(v3 + bv8);
            }
            if (EPI == 3) {
                float i0 = (gn < N)     ? 1.f / auxp[gn]     : 0.f;
                float i1 = (gn + 1 < N) ? 1.f / auxp[gn + 1] : 0.f;
                v0 *= i0; v1 *= i1; v2 *= i0; v3 *= i1;
            }
            if (OU32) {
                if (gn < N)     C32[(size_t)gm * ldc + gn]           = f2tf32(v0);
                if (gn + 1 < N) C32[(size_t)gm * ldc + gn + 1]       = f2tf32(v1);
                if (gn < N)     C32[(size_t)(gm + 8) * ldc + gn]     = f2tf32(v2);
                if (gn + 1 < N) C32[(size_t)(gm + 8) * ldc + gn + 1] = f2tf32(v3);
            } else {
                if (gn < N)     Cf[(size_t)gm * ldc + gn]           = v0;
                if (gn + 1 < N) Cf[(size_t)gm * ldc + gn + 1]       = v1;
                if (gn < N)     Cf[(size_t)(gm + 8) * ldc + gn]     = v2;
                if (gn + 1 < N) Cf[(size_t)(gm + 8) * ldc + gn + 1] = v3;
            }
        }
    }
}

// ============================================================
// gemm_big: exp-scores + row sums. tf32 MMA, BK=16.
// ============================================================
__global__ void __launch_bounds__(256) gemm_big_k(
    const uint32_t* __restrict__ Aq,
    const uint32_t* __restrict__ Bk,
    uint32_t* __restrict__ Cs,
    float* __restrict__ rs)
{
    __shared__ uint32_t As[2][16][136];
    __shared__ uint32_t Bs[2][16][136];
    const uint32_t* Ab = Aq + (size_t)blockIdx.z * C * P;
    const uint32_t* Bb = Bk + (size_t)blockIdx.z * C * D;
    uint32_t* Cb = Cs + (size_t)blockIdx.z * (size_t)P * D;
    float* rsb = rs + (size_t)blockIdx.z * P;

    const int m0 = blockIdx.y * 128, n0 = blockIdx.x * 128;
    const int tid = threadIdx.x;
    const int kf = tid >> 5, e4 = (tid & 31) * 4;
    const int warp = tid >> 5, lane = tid & 31;
    const int g = lane >> 2, t = lane & 3;
    const int wm = warp & 3, wn = warp >> 2;
    const int m0w = wm * 32, n0w = wn * 64;

    float acc[2][8][4];
    #pragma unroll
    for (int i = 0; i < 2; i++)
        #pragma unroll
        for (int j = 0; j < 8; j++)
            #pragma unroll
            for (int r = 0; r < 4; r++) acc[i][j][r] = 0.f;

    uint4 ra0, ra1, rb0, rb1;
    auto ld4A = [&](int krow, uint4& r) {
        const uint32_t* src = Ab + (size_t)krow * P;
        int m = m0 + e4;
        if (m + 3 < P) r = *(const uint4*)(src + m);
        else {
            r.x = (m+0 < P) ? src[m+0] : 0u;
            r.y = (m+1 < P) ? src[m+1] : 0u;
            r.z = (m+2 < P) ? src[m+2] : 0u;
            r.w = (m+3 < P) ? src[m+3] : 0u;
        }
    };
    auto ld4B = [&](int krow, uint4& r) {
        const uint32_t* src = Bb + (size_t)krow * D;
        int n = n0 + e4;
        if (n + 3 < D) r = *(const uint4*)(src + n);
        else {
            r.x = (n+0 < D) ? src[n+0] : 0u;
            r.y = (n+1 < D) ? src[n+1] : 0u;
            r.z = (n+2 < D) ? src[n+2] : 0u;
            r.w = (n+3 < D) ? src[n+3] : 0u;
        }
    };
    auto loadReg = [&](int k0) {
        ld4A(k0 + kf, ra0);
        ld4A(k0 + kf + 8, ra1);
        ld4B(k0 + kf, rb0);
        ld4B(k0 + kf + 8, rb1);
    };
    auto writeS = [&](int buf) {
        *(uint4*)&As[buf][kf][e4]   = ra0;
        *(uint4*)&As[buf][kf+8][e4] = ra1;
        *(uint4*)&Bs[buf][kf][e4]   = rb0;
        *(uint4*)&Bs[buf][kf+8][e4] = rb1;
    };

    loadReg(0);
    writeS(0);
    __syncthreads();

    int buf = 0;
    for (int k0 = 0; k0 < C; k0 += 16) {
        bool nxt = (k0 + 16) < C;
        if (nxt) loadReg(k0 + 16);

        #pragma unroll
        for (int ks = 0; ks < 2; ks++) {
            int kb = ks * 8;
            uint32_t af[2][4], bf[8][2];
            #pragma unroll
            for (int mt = 0; mt < 2; mt++) {
                int mb = m0w + mt * 16 + g;
                af[mt][0] = As[buf][kb + t][mb];
                af[mt][1] = As[buf][kb + t][mb + 8];
                af[mt][2] = As[buf][kb + t + 4][mb];
                af[mt][3] = As[buf][kb + t + 4][mb + 8];
            }
            #pragma unroll
            for (int nt = 0; nt < 8; nt++) {
                int nb = n0w + nt * 8 + g;
                bf[nt][0] = Bs[buf][kb + t][nb];
                bf[nt][1] = Bs[buf][kb + t + 4][nb];
            }
            #pragma unroll
            for (int mt = 0; mt < 2; mt++)
                #pragma unroll
                for (int nt = 0; nt < 8; nt++)
                    mma_tf32(acc[mt][nt][0], acc[mt][nt][1], acc[mt][nt][2], acc[mt][nt][3],
                             af[mt][0], af[mt][1], af[mt][2], af[mt][3],
                             bf[nt][0], bf[nt][1]);
        }

        if (nxt) {
            writeS(buf ^ 1);
            __syncthreads();
            buf ^= 1;
        }
    }

    #pragma unroll
    for (int mt = 0; mt < 2; mt++) {
        int gm = m0 + m0w + mt * 16 + g;
        float s0 = 0.f, s1 = 0.f;
        #pragma unroll
        for (int nt = 0; nt < 8; nt++) {
            int gn = n0 + n0w + nt * 8 + 2 * t;
            bool c0 = (gn < D), c1 = (gn + 1 < D);
            float e0 = __expf(acc[mt][nt][0]);
            float e1 = __expf(acc[mt][nt][1]);
            float e2 = __expf(acc[mt][nt][2]);
            float e3 = __expf(acc[mt][nt][3]);
            if (gm < P) {
                if (c0) Cb[(size_t)gm * D + gn]     = f2tf32(e0);
                if (c1) Cb[(size_t)gm * D + gn + 1] = f2tf32(e1);
            }
            if (gm + 8 < P) {
                if (c0) Cb[(size_t)(gm + 8) * D + gn]     = f2tf32(e2);
                if (c1) Cb[(size_t)(gm + 8) * D + gn + 1] = f2tf32(e3);
            }
            s0 += (c0 ? e0 : 0.f) + (c1 ? e1 : 0.f);
            s1 += (c0 ? e2 : 0.f) + (c1 ? e3 : 0.f);
        }
        s0 += __shfl_xor_sync(0xffffffff, s0, 1);
        s0 += __shfl_xor_sync(0xffffffff, s0, 2);
        s1 += __shfl_xor_sync(0xffffffff, s1, 1);
        s1 += __shfl_xor_sync(0xffffffff, s1, 2);
        if (t == 0) {
            if (gm < P)     atomicAdd(&rsb[gm], s0);
            if (gm + 8 < P) atomicAdd(&rsb[gm + 8], s1);
        }
    }
}

// -------- beff = b_h + W_h[:,2C:3C] @ v_c; v_c from constant c0 --------
__global__ void beff_k(const float* __restrict__ w_vc, const float* __restrict__ c0,
                       const float* __restrict__ w_h, const float* __restrict__ b_h,
                       float* __restrict__ beff)
{
    __shared__ float vc[C];
    int c = threadIdx.x;
    float s = 0.f;
    for (int ci = 0; ci < C; ci++) {
        float ws = 0.f;
        #pragma unroll
        for (int t = 0; t < 9; t++) ws += w_vc[((size_t)c * C + ci) * 9 + t];
        s += ws * c0[ci];
    }
    vc[c] = s;
    __syncthreads();
    float r = b_h[c];
    for (int j = 0; j < C; j++) r += w_h[(size_t)c * (3*C) + 2*C + j] * vc[j];
    beff[c] = r;
}

extern "C" void kernel_launch(void* const* d_in, const int* in_sizes, int n_in,
                              void* d_out, int out_size)
{
    const float* inp  = (const float*)d_in[0];
    const float* c0   = (const float*)d_in[1];
    const float* w_x  = (const float*)d_in[2];
    const float* b_x  = (const float*)d_in[3];
    const float* w_qx = (const float*)d_in[4];
    const float* w_kx = (const float*)d_in[6];
    const float* w_vx = (const float*)d_in[8];
    const float* w_vc = (const float*)d_in[9];
    const float* w_h  = (const float*)d_in[14];
    const float* b_h  = (const float*)d_in[15];
    const float* w_o  = (const float*)d_in[16];
    const float* b_o  = (const float*)d_in[17];
    float* out = (float*)d_out;

    uint32_t *xa, *q, *k, *v, *sc, *h;
    float *rs, *beff;
    cudaGetSymbolAddress((void**)&xa,   g_xa);
    cudaGetSymbolAddress((void**)&q,    g_q);
    cudaGetSymbolAddress((void**)&k,    g_k);
    cudaGetSymbolAddress((void**)&v,    g_v);
    cudaGetSymbolAddress((void**)&sc,   g_sc);
    cudaGetSymbolAddress((void**)&rs,   g_rs);
    cudaGetSymbolAddress((void**)&h,    g_h);
    cudaGetSymbolAddress((void**)&beff, g_beff);
    uint32_t *wx, *wh, *wo;
    cudaGetSymbolAddress((void**)&wx, g_wx);
    cudaGetSymbolAddress((void**)&wh, g_wh);
    cudaGetSymbolAddress((void**)&wo, g_wo);

    const int NT128 = (P + 127) / 128;   // 11

    // constants and weight pre-conversion
    beff_k<<<1, C>>>(w_vc, c0, w_h, b_h, beff);
    preconv_k<<<(C*KC + 255)/256, 256>>>(w_x, w_qx, w_kx, w_vx, w_h, w_o);
    zero_rs_k<<<(NB*P + 255)/256, 256>>>();

    // x = W_x @ inp + b_x -> g_xa rows [0,128) as tf32 bits
    gemm128n_k<0,1,false,true><<<dim3(NT128, 2, NB), 128>>>(
        wx, 0, C, inp, (size_t)C*P, P, xa, (size_t)2*C*P, P, P, C, b_x, 0);

    // q/k/v 3x3 convs, tf32 MMA mega-launch
    qkv_mega_k<<<dim3(62, 1, NB), 128>>>(xa, q, k, v);

    // ex[p,d] = exp(q^T k) + row sums (fused)
    gemm_big_k<<<dim3((D + 127)/128, (P + 127)/128, NB), 256>>>(q, k, sc, rs);

    // a0[c,p] = (v @ ex^T)[c,p] / rs[p] -> g_xa rows [128,256)
    gemm128n_k<1,3,true,true><<<dim3(NT128, 2, NB), 128>>>(
        v, (size_t)C*D, D, sc, (size_t)P*D, D, xa + (size_t)C*P, (size_t)2*C*P, P,
        P, D, rs, P);

    // h = tanh(W_h[:, :2C] @ [x; a0] + beff)
    gemm128n_k<0,2,true,true><<<dim3(NT128, 2, NB), 128>>>(
        wh, 0, 3*C, xa, (size_t)2*C*P, P, h, (size_t)C*P, P, P, 2*C, beff, 0);

    // out = W_o @ h + b_o  (fp32 output)
    gemm128n_k<0,1,true,false><<<dim3(NT128, 2, NB), 128>>>(
        wo, 0, C, h, (size_t)C*P, P, out, (size_t)C*P, P, P, C, b_o, 0);
}

// round 13
// speedup vs baseline: 1.0406x; 1.0406x over previous
#include <cuda_runtime.h>
#include <cstdint>
#include <cstddef>

// Problem dims
#define NB 8
#define C 128
#define HH 36
#define WW 36
#define P (HH*WW)          // 1296 query tokens
#define HV 34
#define WV 34
#define D (HV*WV)          // 1156 key/value tokens
#define KC (C*9)           // 1152 im2col K

// -------- scratch (static device memory; no allocation APIs) --------
__device__ uint32_t g_xa[(size_t)NB*2*C*P];   // rows 0..127: x, rows 128..255: a0
__device__ uint32_t g_q[(size_t)NB*C*P];
__device__ uint32_t g_k[(size_t)NB*C*D];
__device__ uint32_t g_v[(size_t)NB*C*D];
__device__ uint32_t g_sc[(size_t)NB*(size_t)P*D]; // exp(scores) tf32 bits
__device__ float    g_rs[(size_t)NB*P];           // row sums of exp
__device__ uint32_t g_h[(size_t)NB*C*P];
__device__ float    g_beff[C];
__device__ uint32_t g_wx[C*C];
__device__ uint32_t g_wq[C*KC];
__device__ uint32_t g_wk[C*KC];
__device__ uint32_t g_wv[C*KC];
__device__ uint32_t g_wh[C*3*C];
__device__ uint32_t g_wo[C*C];

// -------- tf32 helpers --------
__device__ __forceinline__ uint32_t f2tf32(float f) {
    uint32_t u;
    asm("cvt.rna.tf32.f32 %0, %1;" : "=r"(u) : "f"(f));
    return u;
}

__device__ __forceinline__ void mma_tf32(
    float& c0, float& c1, float& c2, float& c3,
    uint32_t a0, uint32_t a1, uint32_t a2, uint32_t a3,
    uint32_t b0, uint32_t b1)
{
    asm volatile(
        "mma.sync.aligned.m16n8k8.row.col.f32.tf32.tf32.f32 "
        "{%0,%1,%2,%3}, {%4,%5,%6,%7}, {%8,%9}, {%0,%1,%2,%3};"
        : "+f"(c0), "+f"(c1), "+f"(c2), "+f"(c3)
        : "r"(a0), "r"(a1), "r"(a2), "r"(a3), "r"(b0), "r"(b1));
}

// -------- weight pre-conversion (fp32 -> tf32 bits) --------
__global__ void preconv_k(const float* __restrict__ wx, const float* __restrict__ wq,
                          const float* __restrict__ wk, const float* __restrict__ wv,
                          const float* __restrict__ wh, const float* __restrict__ wo)
{
    int i = blockIdx.x * 256 + threadIdx.x;
    if (i < C*C)   { g_wx[i] = f2tf32(wx[i]); g_wo[i] = f2tf32(wo[i]); }
    if (i < C*3*C) g_wh[i] = f2tf32(wh[i]);
    if (i < C*KC)  {
        g_wq[i] = f2tf32(wq[i]);
        g_wk[i] = f2tf32(wk[i]);
        g_wv[i] = f2tf32(wv[i]);
    }
}

__global__ void zero_rs_k()
{
    int i = blockIdx.x * 256 + threadIdx.x;
    if (i < NB * P) g_rs[i] = 0.f;
}

// ============================================================
// qkv_mega: all three 3x3 conv GEMMs in ONE launch, tf32 MMA core.
// CTA tile 64(m) x 128(n), 128 threads = 4 warps, warp tile 32x64.
// ============================================================
__global__ void __launch_bounds__(128) qkv_mega_k(
    const uint32_t* __restrict__ xa,
    uint32_t* __restrict__ qo, uint32_t* __restrict__ ko, uint32_t* __restrict__ vo)
{
    __shared__ uint32_t As[2][16][72];
    __shared__ uint32_t Bs[2][16][136];

    const int bz = blockIdx.z;
    const int tile = blockIdx.x;
    bool qmode; int my, nx;
    if (tile < 22) { qmode = true;  my = tile / 11; nx = tile % 11; }
    else { int t2 = tile - 22; qmode = false; my = t2 / 10; nx = t2 % 10; }

    const uint32_t* A = qmode ? g_wq : ((my < 2) ? g_wk : g_wv);
    const int m0 = qmode ? my * 64 : (my & 1) * 64;
    const int Nn = qmode ? P : D;
    uint32_t* Cp = qmode ? (qo + (size_t)bz * C * P)
                         : ((my < 2) ? ko : vo) + (size_t)bz * C * D;
    const uint32_t* B = xa + (size_t)bz * 2 * C * P;
    const int n0 = nx * 128;
    const int ldc = Nn;

    const int tid = threadIdx.x;
    const int warp = tid >> 5, lane = tid & 31;
    const int g = lane >> 2, t = lane & 3;
    const int wm = warp & 1, wn = warp >> 1;
    const int m0w = wm * 32, n0w = wn * 64;

    const int ka = tid & 15;
    const int ma = tid >> 4;

    int p = n0 + tid;
    bool npred; int iy, ix;
    if (qmode) { npred = (p < P); if (p >= P) p = 0; iy = p / WW; ix = p % WW; }
    else       { npred = (p < D); if (p >= D) p = 0; iy = p / WV; ix = p % WV; }

    float acc[2][8][4];
    #pragma unroll
    for (int i = 0; i < 2; i++)
        #pragma unroll
        for (int j = 0; j < 8; j++)
            #pragma unroll
            for (int r = 0; r < 4; r++) acc[i][j][r] = 0.f;

    uint32_t ra[8], rb[16];

    auto loadAB = [&](int k0) {
        int ci_a = (k0 + ka) & 127, t_a = (k0 + ka) >> 7;
        #pragma unroll
        for (int i = 0; i < 8; i++) {
            int m = m0 + ma + 8 * i;
            ra[i] = A[(size_t)m * KC + ci_a * 9 + t_a];
        }
        int tt = k0 >> 7;
        int ky = tt / 3, kx = tt - ky * 3;
        int cb = k0 & 127;
        if (qmode) {
            int sy = iy + ky - 1, sx = ix + kx - 1;
            bool pr = npred && sy >= 0 && sy < HH && sx >= 0 && sx < WW;
            int rowb = sy * WW + sx;
            #pragma unroll
            for (int i = 0; i < 16; i++)
                rb[i] = pr ? B[(size_t)(cb + i) * P + rowb] : 0u;
        } else {
            int rowb = (iy + ky) * WW + (ix + kx);
            #pragma unroll
            for (int i = 0; i < 16; i++)
                rb[i] = npred ? B[(size_t)(cb + i) * P + rowb] : 0u;
        }
    };

    auto writeS = [&](int buf) {
        #pragma unroll
        for (int i = 0; i < 8; i++) As[buf][ka][ma + 8 * i] = ra[i];
        #pragma unroll
        for (int i = 0; i < 16; i++) Bs[buf][i][tid] = rb[i];
    };

    loadAB(0);
    writeS(0);
    __syncthreads();

    int buf = 0;
    for (int k0 = 0; k0 < KC; k0 += 16) {
        bool nxt = (k0 + 16) < KC;
        if (nxt) loadAB(k0 + 16);

        #pragma unroll
        for (int ks = 0; ks < 2; ks++) {
            int kb = ks * 8;
            uint32_t af[2][4], bf[8][2];
            #pragma unroll
            for (int mt = 0; mt < 2; mt++) {
                int mb = m0w + mt * 16 + g;
                af[mt][0] = As[buf][kb + t][mb];
                af[mt][1] = As[buf][kb + t][mb + 8];
                af[mt][2] = As[buf][kb + t + 4][mb];
                af[mt][3] = As[buf][kb + t + 4][mb + 8];
            }
            #pragma unroll
            for (int nt = 0; nt < 8; nt++) {
                int nb = n0w + nt * 8 + g;
                bf[nt][0] = Bs[buf][kb + t][nb];
                bf[nt][1] = Bs[buf][kb + t + 4][nb];
            }
            #pragma unroll
            for (int mt = 0; mt < 2; mt++)
                #pragma unroll
                for (int nt = 0; nt < 8; nt++)
                    mma_tf32(acc[mt][nt][0], acc[mt][nt][1], acc[mt][nt][2], acc[mt][nt][3],
                             af[mt][0], af[mt][1], af[mt][2], af[mt][3],
                             bf[nt][0], bf[nt][1]);
        }

        if (nxt) {
            writeS(buf ^ 1);
            __syncthreads();
            buf ^= 1;
        }
    }

    #pragma unroll
    for (int mt = 0; mt < 2; mt++) {
        int gm = m0 + m0w + mt * 16 + g;
        #pragma unroll
        for (int nt = 0; nt < 8; nt++) {
            int gn = n0 + n0w + nt * 8 + 2 * t;
            if (gn < Nn)     Cp[(size_t)gm * ldc + gn]           = f2tf32(acc[mt][nt][0]);
            if (gn + 1 < Nn) Cp[(size_t)gm * ldc + gn + 1]       = f2tf32(acc[mt][nt][1]);
            if (gn < Nn)     Cp[(size_t)(gm + 8) * ldc + gn]     = f2tf32(acc[mt][nt][2]);
            if (gn + 1 < Nn) Cp[(size_t)(gm + 8) * ldc + gn + 1] = f2tf32(acc[mt][nt][3]);
        }
    }
}

// ============================================================
// gemm64t: tf32 MMA 64x64 GEMM (R11-proven; used for short-K GEMMs).
// BMODE: 0 = B plain [K][N], 1 = B transposed [N][K].
// BRAW: B already tf32 bits vs fp32. EPI: 0/1 bias/2 tanh/3 colscale.
// OU32: write tf32 bits vs fp32.
// ============================================================
template<int BMODE, int EPI, bool BRAW, bool OU32>
__global__ void __launch_bounds__(128) gemm64t_k(
    const uint32_t* __restrict__ A, size_t sA, int lda,
    const void* __restrict__ Bv, size_t sB, int ldb,
    void* __restrict__ Cv, size_t sC, int ldc,
    int N, int K,
    const float* __restrict__ aux, size_t sAux)
{
    __shared__ uint32_t As[2][16][72];
    __shared__ uint32_t Bs[2][16][72];
    A += (size_t)blockIdx.z * sA;
    const uint32_t* B32 = (const uint32_t*)Bv + (BRAW ? (size_t)blockIdx.z * sB : 0);
    const float*    Bf  = (const float*)Bv    + (BRAW ? 0 : (size_t)blockIdx.z * sB);
    uint32_t* C32 = (uint32_t*)Cv + (size_t)blockIdx.z * sC;
    float*    Cf  = (float*)Cv    + (size_t)blockIdx.z * sC;
    const float* auxp = aux + (size_t)blockIdx.z * sAux;

    const int m0 = blockIdx.y * 64, n0 = blockIdx.x * 64;
    const int tid = threadIdx.x;
    const int warp = tid >> 5, lane = tid & 31;
    const int g = lane >> 2, t = lane & 3;
    const int wm = warp & 1, wn = warp >> 1;
    const int m0w = wm * 32, n0w = wn * 32;

    const int ka = tid & 15;
    const int ma = tid >> 4;
    const int nb64 = tid & 63;
    const int kb2 = tid >> 6;
    const int kb16 = tid & 15;

    float acc[2][4][4];
    #pragma unroll
    for (int i = 0; i < 2; i++)
        #pragma unroll
        for (int j = 0; j < 4; j++)
            #pragma unroll
            for (int r = 0; r < 4; r++) acc[i][j][r] = 0.f;

    uint32_t ra[8], rb[8];

    auto ldB = [&](int gk, int gn) -> uint32_t {
        if (gn >= N || gk >= K) return 0u;
        if (BRAW) return B32[(size_t)(BMODE == 1 ? gn : gk) * ldb + (BMODE == 1 ? gk : gn)];
        else      return f2tf32(Bf[(size_t)(BMODE == 1 ? gn : gk) * ldb + (BMODE == 1 ? gk : gn)]);
    };

    auto loadAB = [&](int k0) {
        #pragma unroll
        for (int i = 0; i < 8; i++) {
            int gk = k0 + ka;
            int m = m0 + ma + 8 * i;
            ra[i] = (gk < K) ? A[(size_t)m * lda + gk] : 0u;
        }
        if (BMODE == 0) {
            #pragma unroll
            for (int i = 0; i < 8; i++)
                rb[i] = ldB(k0 + kb2 + 2 * i, n0 + nb64);
        } else {
            #pragma unroll
            for (int i = 0; i < 8; i++)
                rb[i] = ldB(k0 + kb16, n0 + (tid >> 4) + 8 * i);
        }
    };

    auto writeS = [&](int buf) {
        #pragma unroll
        for (int i = 0; i < 8; i++) As[buf][ka][ma + 8 * i] = ra[i];
        if (BMODE == 1) {
            #pragma unroll
            for (int i = 0; i < 8; i++) Bs[buf][kb16][(tid >> 4) + 8 * i] = rb[i];
        } else {
            #pragma unroll
            for (int i = 0; i < 8; i++) Bs[buf][kb2 + 2 * i][nb64] = rb[i];
        }
    };

    loadAB(0);
    writeS(0);
    __syncthreads();

    int buf = 0;
    for (int k0 = 0; k0 < K; k0 += 16) {
        bool nxt = (k0 + 16) < K;
        if (nxt) loadAB(k0 + 16);

        #pragma unroll
        for (int ks = 0; ks < 2; ks++) {
            int kb = ks * 8;
            uint32_t af[2][4], bf[4][2];
            #pragma unroll
            for (int mt = 0; mt < 2; mt++) {
                int mb = m0w + mt * 16 + g;
                af[mt][0] = As[buf][kb + t][mb];
                af[mt][1] = As[buf][kb + t][mb + 8];
                af[mt][2] = As[buf][kb + t + 4][mb];
                af[mt][3] = As[buf][kb + t + 4][mb + 8];
            }
            #pragma unroll
            for (int nt = 0; nt < 4; nt++) {
                int nb = n0w + nt * 8 + g;
                bf[nt][0] = Bs[buf][kb + t][nb];
                bf[nt][1] = Bs[buf][kb + t + 4][nb];
            }
            #pragma unroll
            for (int mt = 0; mt < 2; mt++)
                #pragma unroll
                for (int nt = 0; nt < 4; nt++)
                    mma_tf32(acc[mt][nt][0], acc[mt][nt][1], acc[mt][nt][2], acc[mt][nt][3],
                             af[mt][0], af[mt][1], af[mt][2], af[mt][3],
                             bf[nt][0], bf[nt][1]);
        }

        if (nxt) {
            writeS(buf ^ 1);
            __syncthreads();
            buf ^= 1;
        }
    }

    #pragma unroll
    for (int mt = 0; mt < 2; mt++) {
        int gm = m0 + m0w + mt * 16 + g;
        float bv0 = (EPI == 1 || EPI == 2) ? auxp[gm] : 0.f;
        float bv8 = (EPI == 1 || EPI == 2) ? auxp[gm + 8] : 0.f;
        #pragma unroll
        for (int nt = 0; nt < 4; nt++) {
            int gn = n0 + n0w + nt * 8 + 2 * t;
            float v0 = acc[mt][nt][0], v1 = acc[mt][nt][1];
            float v2 = acc[mt][nt][2], v3 = acc[mt][nt][3];
            if (EPI == 1) { v0 += bv0; v1 += bv0; v2 += bv8; v3 += bv8; }
            if (EPI == 2) {
                v0 = tanhf(v0 + bv0); v1 = tanhf(v1 + bv0);
                v2 = tanhf(v2 + bv8); v3 = tanhf(v3 + bv8);
            }
            if (EPI == 3) {
                float i0 = (gn < N)     ? 1.f / auxp[gn]     : 0.f;
                float i1 = (gn + 1 < N) ? 1.f / auxp[gn + 1] : 0.f;
                v0 *= i0; v1 *= i1; v2 *= i0; v3 *= i1;
            }
            if (OU32) {
                if (gn < N)     C32[(size_t)gm * ldc + gn]           = f2tf32(v0);
                if (gn + 1 < N) C32[(size_t)gm * ldc + gn + 1]       = f2tf32(v1);
                if (gn < N)     C32[(size_t)(gm + 8) * ldc + gn]     = f2tf32(v2);
                if (gn + 1 < N) C32[(size_t)(gm + 8) * ldc + gn + 1] = f2tf32(v3);
            } else {
                if (gn < N)     Cf[(size_t)gm * ldc + gn]           = v0;
                if (gn + 1 < N) Cf[(size_t)gm * ldc + gn + 1]       = v1;
                if (gn < N)     Cf[(size_t)(gm + 8) * ldc + gn]     = v2;
                if (gn + 1 < N) Cf[(size_t)(gm + 8) * ldc + gn + 1] = v3;
            }
        }
    }
}

// ============================================================
// gemm128n: 64(m) x 128(n) tile GEMM (long-K only: PV).
// BMODE 1 (B transposed [N][K]), BRAW, EPI 3 (col scale), OU32.
// ============================================================
__global__ void __launch_bounds__(128) gemm128n_pv_k(
    const uint32_t* __restrict__ A, size_t sA, int lda,
    const uint32_t* __restrict__ B32, size_t sB, int ldb,
    uint32_t* __restrict__ C32, size_t sC, int ldc,
    int N, int K,
    const float* __restrict__ aux, size_t sAux)
{
    __shared__ uint32_t As[2][16][72];
    __shared__ uint32_t Bs[2][16][136];
    A   += (size_t)blockIdx.z * sA;
    B32 += (size_t)blockIdx.z * sB;
    C32 += (size_t)blockIdx.z * sC;
    const float* auxp = aux + (size_t)blockIdx.z * sAux;

    const int m0 = blockIdx.y * 64, n0 = blockIdx.x * 128;
    const int tid = threadIdx.x;
    const int warp = tid >> 5, lane = tid & 31;
    const int g = lane >> 2, t = lane & 3;
    const int wm = warp & 1, wn = warp >> 1;
    const int m0w = wm * 32, n0w = wn * 64;

    const int ka = tid & 15;
    const int ma = tid >> 4;

    float acc[2][8][4];
    #pragma unroll
    for (int i = 0; i < 2; i++)
        #pragma unroll
        for (int j = 0; j < 8; j++)
            #pragma unroll
            for (int r = 0; r < 4; r++) acc[i][j][r] = 0.f;

    uint32_t ra[8], rb[16];

    auto loadAB = [&](int k0) {
        #pragma unroll
        for (int i = 0; i < 8; i++) {
            int gk = k0 + ka;
            int m = m0 + ma + 8 * i;
            ra[i] = (gk < K) ? A[(size_t)m * lda + gk] : 0u;
        }
        int gk = k0 + ka;
        bool kok = (gk < K);
        #pragma unroll
        for (int i = 0; i < 16; i++) {
            int gn = n0 + ma + 8 * i;
            rb[i] = (kok && gn < N) ? B32[(size_t)gn * ldb + gk] : 0u;
        }
    };

    auto writeS = [&](int buf) {
        #pragma unroll
        for (int i = 0; i < 8; i++) As[buf][ka][ma + 8 * i] = ra[i];
        #pragma unroll
        for (int i = 0; i < 16; i++) Bs[buf][ka][ma + 8 * i] = rb[i];
    };

    loadAB(0);
    writeS(0);
    __syncthreads();

    int buf = 0;
    for (int k0 = 0; k0 < K; k0 += 16) {
        bool nxt = (k0 + 16) < K;
        if (nxt) loadAB(k0 + 16);

        #pragma unroll
        for (int ks = 0; ks < 2; ks++) {
            int kb = ks * 8;
            uint32_t af[2][4], bf[8][2];
            #pragma unroll
            for (int mt = 0; mt < 2; mt++) {
                int mb = m0w + mt * 16 + g;
                af[mt][0] = As[buf][kb + t][mb];
                af[mt][1] = As[buf][kb + t][mb + 8];
                af[mt][2] = As[buf][kb + t + 4][mb];
                af[mt][3] = As[buf][kb + t + 4][mb + 8];
            }
            #pragma unroll
            for (int nt = 0; nt < 8; nt++) {
                int nb = n0w + nt * 8 + g;
                bf[nt][0] = Bs[buf][kb + t][nb];
                bf[nt][1] = Bs[buf][kb + t + 4][nb];
            }
            #pragma unroll
            for (int mt = 0; mt < 2; mt++)
                #pragma unroll
                for (int nt = 0; nt < 8; nt++)
                    mma_tf32(acc[mt][nt][0], acc[mt][nt][1], acc[mt][nt][2], acc[mt][nt][3],
                             af[mt][0], af[mt][1], af[mt][2], af[mt][3],
                             bf[nt][0], bf[nt][1]);
        }

        if (nxt) {
            writeS(buf ^ 1);
            __syncthreads();
            buf ^= 1;
        }
    }

    #pragma unroll
    for (int mt = 0; mt < 2; mt++) {
        int gm = m0 + m0w + mt * 16 + g;
        #pragma unroll
        for (int nt = 0; nt < 8; nt++) {
            int gn = n0 + n0w + nt * 8 + 2 * t;
            float i0 = (gn < N)     ? 1.f / auxp[gn]     : 0.f;
            float i1 = (gn + 1 < N) ? 1.f / auxp[gn + 1] : 0.f;
            float v0 = acc[mt][nt][0] * i0, v1 = acc[mt][nt][1] * i1;
            float v2 = acc[mt][nt][2] * i0, v3 = acc[mt][nt][3] * i1;
            if (gn < N)     C32[(size_t)gm * ldc + gn]           = f2tf32(v0);
            if (gn + 1 < N) C32[(size_t)gm * ldc + gn + 1]       = f2tf32(v1);
            if (gn < N)     C32[(size_t)(gm + 8) * ldc + gn]     = f2tf32(v2);
            if (gn + 1 < N) C32[(size_t)(gm + 8) * ldc + gn + 1] = f2tf32(v3);
        }
    }
}

// ============================================================
// gemm_big: exp-scores + row sums. tf32 MMA, BK=16.
// ============================================================
__global__ void __launch_bounds__(256) gemm_big_k(
    const uint32_t* __restrict__ Aq,
    const uint32_t* __restrict__ Bk,
    uint32_t* __restrict__ Cs,
    float* __restrict__ rs)
{
    __shared__ uint32_t As[2][16][136];
    __shared__ uint32_t Bs[2][16][136];
    const uint32_t* Ab = Aq + (size_t)blockIdx.z * C * P;
    const uint32_t* Bb = Bk + (size_t)blockIdx.z * C * D;
    uint32_t* Cb = Cs + (size_t)blockIdx.z * (size_t)P * D;
    float* rsb = rs + (size_t)blockIdx.z * P;

    const int m0 = blockIdx.y * 128, n0 = blockIdx.x * 128;
    const int tid = threadIdx.x;
    const int kf = tid >> 5, e4 = (tid & 31) * 4;
    const int warp = tid >> 5, lane = tid & 31;
    const int g = lane >> 2, t = lane & 3;
    const int wm = warp & 3, wn = warp >> 2;
    const int m0w = wm * 32, n0w = wn * 64;

    float acc[2][8][4];
    #pragma unroll
    for (int i = 0; i < 2; i++)
        #pragma unroll
        for (int j = 0; j < 8; j++)
            #pragma unroll
            for (int r = 0; r < 4; r++) acc[i][j][r] = 0.f;

    uint4 ra0, ra1, rb0, rb1;
    auto ld4A = [&](int krow, uint4& r) {
        const uint32_t* src = Ab + (size_t)krow * P;
        int m = m0 + e4;
        if (m + 3 < P) r = *(const uint4*)(src + m);
        else {
            r.x = (m+0 < P) ? src[m+0] : 0u;
            r.y = (m+1 < P) ? src[m+1] : 0u;
            r.z = (m+2 < P) ? src[m+2] : 0u;
            r.w = (m+3 < P) ? src[m+3] : 0u;
        }
    };
    auto ld4B = [&](int krow, uint4& r) {
        const uint32_t* src = Bb + (size_t)krow * D;
        int n = n0 + e4;
        if (n + 3 < D) r = *(const uint4*)(src + n);
        else {
            r.x = (n+0 < D) ? src[n+0] : 0u;
            r.y = (n+1 < D) ? src[n+1] : 0u;
            r.z = (n+2 < D) ? src[n+2] : 0u;
            r.w = (n+3 < D) ? src[n+3] : 0u;
        }
    };
    auto loadReg = [&](int k0) {
        ld4A(k0 + kf, ra0);
        ld4A(k0 + kf + 8, ra1);
        ld4B(k0 + kf, rb0);
        ld4B(k0 + kf + 8, rb1);
    };
    auto writeS = [&](int buf) {
        *(uint4*)&As[buf][kf][e4]   = ra0;
        *(uint4*)&As[buf][kf+8][e4] = ra1;
        *(uint4*)&Bs[buf][kf][e4]   = rb0;
        *(uint4*)&Bs[buf][kf+8][e4] = rb1;
    };

    loadReg(0);
    writeS(0);
    __syncthreads();

    int buf = 0;
    for (int k0 = 0; k0 < C; k0 += 16) {
        bool nxt = (k0 + 16) < C;
        if (nxt) loadReg(k0 + 16);

        #pragma unroll
        for (int ks = 0; ks < 2; ks++) {
            int kb = ks * 8;
            uint32_t af[2][4], bf[8][2];
            #pragma unroll
            for (int mt = 0; mt < 2; mt++) {
                int mb = m0w + mt * 16 + g;
                af[mt][0] = As[buf][kb + t][mb];
                af[mt][1] = As[buf][kb + t][mb + 8];
                af[mt][2] = As[buf][kb + t + 4][mb];
                af[mt][3] = As[buf][kb + t + 4][mb + 8];
            }
            #pragma unroll
            for (int nt = 0; nt < 8; nt++) {
                int nb = n0w + nt * 8 + g;
                bf[nt][0] = Bs[buf][kb + t][nb];
                bf[nt][1] = Bs[buf][kb + t + 4][nb];
            }
            #pragma unroll
            for (int mt = 0; mt < 2; mt++)
                #pragma unroll
                for (int nt = 0; nt < 8; nt++)
                    mma_tf32(acc[mt][nt][0], acc[mt][nt][1], acc[mt][nt][2], acc[mt][nt][3],
                             af[mt][0], af[mt][1], af[mt][2], af[mt][3],
                             bf[nt][0], bf[nt][1]);
        }

        if (nxt) {
            writeS(buf ^ 1);
            __syncthreads();
            buf ^= 1;
        }
    }

    #pragma unroll
    for (int mt = 0; mt < 2; mt++) {
        int gm = m0 + m0w + mt * 16 + g;
        float s0 = 0.f, s1 = 0.f;
        #pragma unroll
        for (int nt = 0; nt < 8; nt++) {
            int gn = n0 + n0w + nt * 8 + 2 * t;
            bool c0 = (gn < D), c1 = (gn + 1 < D);
            float e0 = __expf(acc[mt][nt][0]);
            float e1 = __expf(acc[mt][nt][1]);
            float e2 = __expf(acc[mt][nt][2]);
            float e3 = __expf(acc[mt][nt][3]);
            if (gm < P) {
                if (c0) Cb[(size_t)gm * D + gn]     = f2tf32(e0);
                if (c1) Cb[(size_t)gm * D + gn + 1] = f2tf32(e1);
            }
            if (gm + 8 < P) {
                if (c0) Cb[(size_t)(gm + 8) * D + gn]     = f2tf32(e2);
                if (c1) Cb[(size_t)(gm + 8) * D + gn + 1] = f2tf32(e3);
            }
            s0 += (c0 ? e0 : 0.f) + (c1 ? e1 : 0.f);
            s1 += (c0 ? e2 : 0.f) + (c1 ? e3 : 0.f);
        }
        s0 += __shfl_xor_sync(0xffffffff, s0, 1);
        s0 += __shfl_xor_sync(0xffffffff, s0, 2);
        s1 += __shfl_xor_sync(0xffffffff, s1, 1);
        s1 += __shfl_xor_sync(0xffffffff, s1, 2);
        if (t == 0) {
            if (gm < P)     atomicAdd(&rsb[gm], s0);
            if (gm + 8 < P) atomicAdd(&rsb[gm + 8], s1);
        }
    }
}

// -------- beff = b_h + W_h[:,2C:3C] @ v_c; v_c from constant c0 --------
__global__ void beff_k(const float* __restrict__ w_vc, const float* __restrict__ c0,
                       const float* __restrict__ w_h, const float* __restrict__ b_h,
                       float* __restrict__ beff)
{
    __shared__ float vc[C];
    int c = threadIdx.x;
    float s = 0.f;
    for (int ci = 0; ci < C; ci++) {
        float ws = 0.f;
        #pragma unroll
        for (int t = 0; t < 9; t++) ws += w_vc[((size_t)c * C + ci) * 9 + t];
        s += ws * c0[ci];
    }
    vc[c] = s;
    __syncthreads();
    float r = b_h[c];
    for (int j = 0; j < C; j++) r += w_h[(size_t)c * (3*C) + 2*C + j] * vc[j];
    beff[c] = r;
}

extern "C" void kernel_launch(void* const* d_in, const int* in_sizes, int n_in,
                              void* d_out, int out_size)
{
    const float* inp  = (const float*)d_in[0];
    const float* c0   = (const float*)d_in[1];
    const float* w_x  = (const float*)d_in[2];
    const float* b_x  = (const float*)d_in[3];
    const float* w_qx = (const float*)d_in[4];
    const float* w_kx = (const float*)d_in[6];
    const float* w_vx = (const float*)d_in[8];
    const float* w_vc = (const float*)d_in[9];
    const float* w_h  = (const float*)d_in[14];
    const float* b_h  = (const float*)d_in[15];
    const float* w_o  = (const float*)d_in[16];
    const float* b_o  = (const float*)d_in[17];
    float* out = (float*)d_out;

    uint32_t *xa, *q, *k, *v, *sc, *h;
    float *rs, *beff;
    cudaGetSymbolAddress((void**)&xa,   g_xa);
    cudaGetSymbolAddress((void**)&q,    g_q);
    cudaGetSymbolAddress((void**)&k,    g_k);
    cudaGetSymbolAddress((void**)&v,    g_v);
    cudaGetSymbolAddress((void**)&sc,   g_sc);
    cudaGetSymbolAddress((void**)&rs,   g_rs);
    cudaGetSymbolAddress((void**)&h,    g_h);
    cudaGetSymbolAddress((void**)&beff, g_beff);
    uint32_t *wx, *wh, *wo;
    cudaGetSymbolAddress((void**)&wx, g_wx);
    cudaGetSymbolAddress((void**)&wh, g_wh);
    cudaGetSymbolAddress((void**)&wo, g_wo);

    const int NT_P = (P + 63) / 64;      // 21
    const int NT128 = (P + 127) / 128;   // 11

    // constants and weight pre-conversion
    beff_k<<<1, C>>>(w_vc, c0, w_h, b_h, beff);
    preconv_k<<<(C*KC + 255)/256, 256>>>(w_x, w_qx, w_kx, w_vx, w_h, w_o);
    zero_rs_k<<<(NB*P + 255)/256, 256>>>();

    // x = W_x @ inp + b_x -> g_xa rows [0,128) as tf32 bits  (64x64, short K)
    gemm64t_k<0,1,false,true><<<dim3(NT_P, 2, NB), 128>>>(
        wx, 0, C, inp, (size_t)C*P, P, xa, (size_t)2*C*P, P, P, C, b_x, 0);

    // q/k/v 3x3 convs, tf32 MMA mega-launch
    qkv_mega_k<<<dim3(62, 1, NB), 128>>>(xa, q, k, v);

    // ex[p,d] = exp(q^T k) + row sums (fused)
    gemm_big_k<<<dim3((D + 127)/128, (P + 127)/128, NB), 256>>>(q, k, sc, rs);

    // a0[c,p] = (v @ ex^T)[c,p] / rs[p]  (64x128 tile, long K=D)
    gemm128n_pv_k<<<dim3(NT128, 2, NB), 128>>>(
        v, (size_t)C*D, D, sc, (size_t)P*D, D, xa + (size_t)C*P, (size_t)2*C*P, P,
        P, D, rs, P);

    // h = tanh(W_h[:, :2C] @ [x; a0] + beff)  (64x64, short K)
    gemm64t_k<0,2,true,true><<<dim3(NT_P, 2, NB), 128>>>(
        wh, 0, 3*C, xa, (size_t)2*C*P, P, h, (size_t)C*P, P, P, 2*C, beff, 0);

    // out = W_o @ h + b_o  (fp32 output)  (64x64, short K)
    gemm64t_k<0,1,true,false><<<dim3(NT_P, 2, NB), 128>>>(
        wo, 0, C, h, (size_t)C*P, P, out, (size_t)C*P, P, P, C, b_o, 0);
}

// round 14
// speedup vs baseline: 1.1643x; 1.1189x over previous
#include <cuda_runtime.h>
#include <cstdint>
#include <cstddef>

// Problem dims
#define NB 8
#define C 128
#define HH 36
#define WW 36
#define P (HH*WW)          // 1296 query tokens
#define HV 34
#define WV 34
#define D (HV*WV)          // 1156 key/value tokens
#define KC (C*9)           // 1152 im2col K

// -------- scratch (static device memory; no allocation APIs) --------
__device__ uint32_t g_xa[(size_t)NB*2*C*P];   // rows 0..127: x, rows 128..255: a0
__device__ uint32_t g_q[(size_t)NB*C*P];
__device__ uint32_t g_k[(size_t)NB*C*D];
__device__ uint32_t g_v[(size_t)NB*C*D];
__device__ uint32_t g_sc[(size_t)NB*(size_t)P*D]; // exp(scores) tf32 bits
__device__ float    g_rs[(size_t)NB*P];           // row sums of exp
__device__ uint32_t g_h[(size_t)NB*C*P];
__device__ float    g_beff[C];
__device__ uint32_t g_wx[C*C];
__device__ uint32_t g_wh[C*3*C];
__device__ uint32_t g_wo[C*C];
// qkv weights pre-transposed to [kg][m], kg = t*128 + ci (t-major K order)
__device__ uint32_t g_wqt[KC*C];
__device__ uint32_t g_wkt[KC*C];
__device__ uint32_t g_wvt[KC*C];

// -------- tf32 helpers --------
__device__ __forceinline__ uint32_t f2tf32(float f) {
    uint32_t u;
    asm("cvt.rna.tf32.f32 %0, %1;" : "=r"(u) : "f"(f));
    return u;
}

__device__ __forceinline__ void mma_tf32(
    float& c0, float& c1, float& c2, float& c3,
    uint32_t a0, uint32_t a1, uint32_t a2, uint32_t a3,
    uint32_t b0, uint32_t b1)
{
    asm volatile(
        "mma.sync.aligned.m16n8k8.row.col.f32.tf32.tf32.f32 "
        "{%0,%1,%2,%3}, {%4,%5,%6,%7}, {%8,%9}, {%0,%1,%2,%3};"
        : "+f"(c0), "+f"(c1), "+f"(c2), "+f"(c3)
        : "r"(a0), "r"(a1), "r"(a2), "r"(a3), "r"(b0), "r"(b1));
}

// -------- weight pre-conversion --------
__global__ void preconv_k(const float* __restrict__ wx, const float* __restrict__ wh,
                          const float* __restrict__ wo)
{
    int i = blockIdx.x * 256 + threadIdx.x;
    if (i < C*C)   { g_wx[i] = f2tf32(wx[i]); g_wo[i] = f2tf32(wo[i]); }
    if (i < C*3*C) g_wh[i] = f2tf32(wh[i]);
}

// transpose qkv weights: g_w?t[kg*C + m] = w?[m][ci][t], kg = t*128 + ci
__global__ void preconv_t_k(const float* __restrict__ wq, const float* __restrict__ wk,
                            const float* __restrict__ wv)
{
    int i = blockIdx.x * 256 + threadIdx.x;
    if (i >= KC * C) return;
    int kg = i / C, m = i % C;
    int t = kg >> 7, ci = kg & 127;
    size_t src = ((size_t)m * C + ci) * 9 + t;
    g_wqt[i] = f2tf32(wq[src]);
    g_wkt[i] = f2tf32(wk[src]);
    g_wvt[i] = f2tf32(wv[src]);
}

__global__ void zero_rs_k()
{
    int i = blockIdx.x * 256 + threadIdx.x;
    if (i < NB * P) g_rs[i] = 0.f;
}

// ============================================================
// qkv_mega: all three 3x3 conv GEMMs in ONE launch, tf32 MMA core.
// CTA tile 64(m) x 128(n), 128 threads = 4 warps, warp tile 32x64.
// A read COALESCED from pre-transposed [kg][m] weights.
// ============================================================
__global__ void __launch_bounds__(128) qkv_mega_k(
    const uint32_t* __restrict__ xa,
    uint32_t* __restrict__ qo, uint32_t* __restrict__ ko, uint32_t* __restrict__ vo)
{
    __shared__ uint32_t As[2][16][72];
    __shared__ uint32_t Bs[2][16][136];

    const int bz = blockIdx.z;
    const int tile = blockIdx.x;
    bool qmode; int my, nx;
    if (tile < 22) { qmode = true;  my = tile / 11; nx = tile % 11; }
    else { int t2 = tile - 22; qmode = false; my = t2 / 10; nx = t2 % 10; }

    const uint32_t* At = qmode ? g_wqt : ((my < 2) ? g_wkt : g_wvt);
    const int m0 = qmode ? my * 64 : (my & 1) * 64;
    const int Nn = qmode ? P : D;
    uint32_t* Cp = qmode ? (qo + (size_t)bz * C * P)
                         : ((my < 2) ? ko : vo) + (size_t)bz * C * D;
    const uint32_t* B = xa + (size_t)bz * 2 * C * P;
    const int n0 = nx * 128;
    const int ldc = Nn;

    const int tid = threadIdx.x;
    const int warp = tid >> 5, lane = tid & 31;
    const int g = lane >> 2, t = lane & 3;
    const int wm = warp & 1, wn = warp >> 1;
    const int m0w = wm * 32, n0w = wn * 64;

    // A loader: coalesced. kA = tid>>3 (16 rows), mA0 = (tid&7)*8 (64 m / 8 thr).
    const int kA = tid >> 3;
    const int mA0 = (tid & 7) * 8;

    int p = n0 + tid;
    bool npred; int iy, ix;
    if (qmode) { npred = (p < P); if (p >= P) p = 0; iy = p / WW; ix = p % WW; }
    else       { npred = (p < D); if (p >= D) p = 0; iy = p / WV; ix = p % WV; }

    float acc[2][8][4];
    #pragma unroll
    for (int i = 0; i < 2; i++)
        #pragma unroll
        for (int j = 0; j < 8; j++)
            #pragma unroll
            for (int r = 0; r < 4; r++) acc[i][j][r] = 0.f;

    uint4 ra4[2];
    uint32_t rb[16];

    auto loadAB = [&](int k0) {
        const uint32_t* arow = At + (size_t)(k0 + kA) * C + m0 + mA0;
        ra4[0] = *(const uint4*)(arow);
        ra4[1] = *(const uint4*)(arow + 4);
        int tt = k0 >> 7;
        int ky = tt / 3, kx = tt - ky * 3;
        int cb = k0 & 127;
        if (qmode) {
            int sy = iy + ky - 1, sx = ix + kx - 1;
            bool pr = npred && sy >= 0 && sy < HH && sx >= 0 && sx < WW;
            int rowb = sy * WW + sx;
            #pragma unroll
            for (int i = 0; i < 16; i++)
                rb[i] = pr ? B[(size_t)(cb + i) * P + rowb] : 0u;
        } else {
            int rowb = (iy + ky) * WW + (ix + kx);
            #pragma unroll
            for (int i = 0; i < 16; i++)
                rb[i] = npred ? B[(size_t)(cb + i) * P + rowb] : 0u;
        }
    };

    auto writeS = [&](int buf) {
        *(uint4*)&As[buf][kA][mA0]     = ra4[0];
        *(uint4*)&As[buf][kA][mA0 + 4] = ra4[1];
        #pragma unroll
        for (int i = 0; i < 16; i++) Bs[buf][i][tid] = rb[i];
    };

    loadAB(0);
    writeS(0);
    __syncthreads();

    int buf = 0;
    for (int k0 = 0; k0 < KC; k0 += 16) {
        bool nxt = (k0 + 16) < KC;
        if (nxt) loadAB(k0 + 16);

        #pragma unroll
        for (int ks = 0; ks < 2; ks++) {
            int kb = ks * 8;
            uint32_t af[2][4], bf[8][2];
            #pragma unroll
            for (int mt = 0; mt < 2; mt++) {
                int mb = m0w + mt * 16 + g;
                af[mt][0] = As[buf][kb + t][mb];
                af[mt][1] = As[buf][kb + t][mb + 8];
                af[mt][2] = As[buf][kb + t + 4][mb];
                af[mt][3] = As[buf][kb + t + 4][mb + 8];
            }
            #pragma unroll
            for (int nt = 0; nt < 8; nt++) {
                int nb = n0w + nt * 8 + g;
                bf[nt][0] = Bs[buf][kb + t][nb];
                bf[nt][1] = Bs[buf][kb + t + 4][nb];
            }
            #pragma unroll
            for (int mt = 0; mt < 2; mt++)
                #pragma unroll
                for (int nt = 0; nt < 8; nt++)
                    mma_tf32(acc[mt][nt][0], acc[mt][nt][1], acc[mt][nt][2], acc[mt][nt][3],
                             af[mt][0], af[mt][1], af[mt][2], af[mt][3],
                             bf[nt][0], bf[nt][1]);
        }

        if (nxt) {
            writeS(buf ^ 1);
            __syncthreads();
            buf ^= 1;
        }
    }

    #pragma unroll
    for (int mt = 0; mt < 2; mt++) {
        int gm = m0 + m0w + mt * 16 + g;
        #pragma unroll
        for (int nt = 0; nt < 8; nt++) {
            int gn = n0 + n0w + nt * 8 + 2 * t;
            if (gn < Nn)     Cp[(size_t)gm * ldc + gn]           = f2tf32(acc[mt][nt][0]);
            if (gn + 1 < Nn) Cp[(size_t)gm * ldc + gn + 1]       = f2tf32(acc[mt][nt][1]);
            if (gn < Nn)     Cp[(size_t)(gm + 8) * ldc + gn]     = f2tf32(acc[mt][nt][2]);
            if (gn + 1 < Nn) Cp[(size_t)(gm + 8) * ldc + gn + 1] = f2tf32(acc[mt][nt][3]);
        }
    }
}

// ============================================================
// gemm64t: tf32 MMA 64x64 GEMM (R11-proven; short-K GEMMs + PV).
// BMODE: 0 = B plain [K][N], 1 = B transposed [N][K].
// BRAW: B already tf32 bits vs fp32. EPI: 0/1 bias/2 tanh/3 colscale.
// OU32: write tf32 bits vs fp32.
// ============================================================
template<int BMODE, int EPI, bool BRAW, bool OU32>
__global__ void __launch_bounds__(128) gemm64t_k(
    const uint32_t* __restrict__ A, size_t sA, int lda,
    const void* __restrict__ Bv, size_t sB, int ldb,
    void* __restrict__ Cv, size_t sC, int ldc,
    int N, int K,
    const float* __restrict__ aux, size_t sAux)
{
    __shared__ uint32_t As[2][16][72];
    __shared__ uint32_t Bs[2][16][72];
    A += (size_t)blockIdx.z * sA;
    const uint32_t* B32 = (const uint32_t*)Bv + (BRAW ? (size_t)blockIdx.z * sB : 0);
    const float*    Bf  = (const float*)Bv    + (BRAW ? 0 : (size_t)blockIdx.z * sB);
    uint32_t* C32 = (uint32_t*)Cv + (size_t)blockIdx.z * sC;
    float*    Cf  = (float*)Cv    + (size_t)blockIdx.z * sC;
    const float* auxp = aux + (size_t)blockIdx.z * sAux;

    const int m0 = blockIdx.y * 64, n0 = blockIdx.x * 64;
    const int tid = threadIdx.x;
    const int warp = tid >> 5, lane = tid & 31;
    const int g = lane >> 2, t = lane & 3;
    const int wm = warp & 1, wn = warp >> 1;
    const int m0w = wm * 32, n0w = wn * 32;

    const int ka = tid & 15;
    const int ma = tid >> 4;
    const int nb64 = tid & 63;
    const int kb2 = tid >> 6;
    const int kb16 = tid & 15;

    float acc[2][4][4];
    #pragma unroll
    for (int i = 0; i < 2; i++)
        #pragma unroll
        for (int j = 0; j < 4; j++)
            #pragma unroll
            for (int r = 0; r < 4; r++) acc[i][j][r] = 0.f;

    uint32_t ra[8], rb[8];

    auto ldB = [&](int gk, int gn) -> uint32_t {
        if (gn >= N || gk >= K) return 0u;
        if (BRAW) return B32[(size_t)(BMODE == 1 ? gn : gk) * ldb + (BMODE == 1 ? gk : gn)];
        else      return f2tf32(Bf[(size_t)(BMODE == 1 ? gn : gk) * ldb + (BMODE == 1 ? gk : gn)]);
    };

    auto loadAB = [&](int k0) {
        #pragma unroll
        for (int i = 0; i < 8; i++) {
            int gk = k0 + ka;
            int m = m0 + ma + 8 * i;
            ra[i] = (gk < K) ? A[(size_t)m * lda + gk] : 0u;
        }
        if (BMODE == 0) {
            #pragma unroll
            for (int i = 0; i < 8; i++)
                rb[i] = ldB(k0 + kb2 + 2 * i, n0 + nb64);
        } else {
            #pragma unroll
            for (int i = 0; i < 8; i++)
                rb[i] = ldB(k0 + kb16, n0 + (tid >> 4) + 8 * i);
        }
    };

    auto writeS = [&](int buf) {
        #pragma unroll
        for (int i = 0; i < 8; i++) As[buf][ka][ma + 8 * i] = ra[i];
        if (BMODE == 1) {
            #pragma unroll
            for (int i = 0; i < 8; i++) Bs[buf][kb16][(tid >> 4) + 8 * i] = rb[i];
        } else {
            #pragma unroll
            for (int i = 0; i < 8; i++) Bs[buf][kb2 + 2 * i][nb64] = rb[i];
        }
    };

    loadAB(0);
    writeS(0);
    __syncthreads();

    int buf = 0;
    for (int k0 = 0; k0 < K; k0 += 16) {
        bool nxt = (k0 + 16) < K;
        if (nxt) loadAB(k0 + 16);

        #pragma unroll
        for (int ks = 0; ks < 2; ks++) {
            int kb = ks * 8;
            uint32_t af[2][4], bf[4][2];
            #pragma unroll
            for (int mt = 0; mt < 2; mt++) {
                int mb = m0w + mt * 16 + g;
                af[mt][0] = As[buf][kb + t][mb];
                af[mt][1] = As[buf][kb + t][mb + 8];
                af[mt][2] = As[buf][kb + t + 4][mb];
                af[mt][3] = As[buf][kb + t + 4][mb + 8];
            }
            #pragma unroll
            for (int nt = 0; nt < 4; nt++) {
                int nb = n0w + nt * 8 + g;
                bf[nt][0] = Bs[buf][kb + t][nb];
                bf[nt][1] = Bs[buf][kb + t + 4][nb];
            }
            #pragma unroll
            for (int mt = 0; mt < 2; mt++)
                #pragma unroll
                for (int nt = 0; nt < 4; nt++)
                    mma_tf32(acc[mt][nt][0], acc[mt][nt][1], acc[mt][nt][2], acc[mt][nt][3],
                             af[mt][0], af[mt][1], af[mt][2], af[mt][3],
                             bf[nt][0], bf[nt][1]);
        }

        if (nxt) {
            writeS(buf ^ 1);
            __syncthreads();
            buf ^= 1;
        }
    }

    #pragma unroll
    for (int mt = 0; mt < 2; mt++) {
        int gm = m0 + m0w + mt * 16 + g;
        float bv0 = (EPI == 1 || EPI == 2) ? auxp[gm] : 0.f;
        float bv8 = (EPI == 1 || EPI == 2) ? auxp[gm + 8] : 0.f;
        #pragma unroll
        for (int nt = 0; nt < 4; nt++) {
            int gn = n0 + n0w + nt * 8 + 2 * t;
            float v0 = acc[mt][nt][0], v1 = acc[mt][nt][1];
            float v2 = acc[mt][nt][2], v3 = acc[mt][nt][3];
            if (EPI == 1) { v0 += bv0; v1 += bv0; v2 += bv8; v3 += bv8; }
            if (EPI == 2) {
                v0 = tanhf(v0 + bv0); v1 = tanhf(v1 + bv0);
                v2 = tanhf(v2 + bv8); v3 = tanhf(v3 + bv8);
            }
            if (EPI == 3) {
                float i0 = (gn < N)     ? 1.f / auxp[gn]     : 0.f;
                float i1 = (gn + 1 < N) ? 1.f / auxp[gn + 1] : 0.f;
                v0 *= i0; v1 *= i1; v2 *= i0; v3 *= i1;
            }
            if (OU32) {
                if (gn < N)     C32[(size_t)gm * ldc + gn]           = f2tf32(v0);
                if (gn + 1 < N) C32[(size_t)gm * ldc + gn + 1]       = f2tf32(v1);
                if (gn < N)     C32[(size_t)(gm + 8) * ldc + gn]     = f2tf32(v2);
                if (gn + 1 < N) C32[(size_t)(gm + 8) * ldc + gn + 1] = f2tf32(v3);
            } else {
                if (gn < N)     Cf[(size_t)gm * ldc + gn]           = v0;
                if (gn + 1 < N) Cf[(size_t)gm * ldc + gn + 1]       = v1;
                if (gn < N)     Cf[(size_t)(gm + 8) * ldc + gn]     = v2;
                if (gn + 1 < N) Cf[(size_t)(gm + 8) * ldc + gn + 1] = v3;
            }
        }
    }
}

// ============================================================
// gemm_big: exp-scores + row sums. tf32 MMA, BK=16.
// ============================================================
__global__ void __launch_bounds__(256) gemm_big_k(
    const uint32_t* __restrict__ Aq,
    const uint32_t* __restrict__ Bk,
    uint32_t* __restrict__ Cs,
    float* __restrict__ rs)
{
    __shared__ uint32_t As[2][16][136];
    __shared__ uint32_t Bs[2][16][136];
    const uint32_t* Ab = Aq + (size_t)blockIdx.z * C * P;
    const uint32_t* Bb = Bk + (size_t)blockIdx.z * C * D;
    uint32_t* Cb = Cs + (size_t)blockIdx.z * (size_t)P * D;
    float* rsb = rs + (size_t)blockIdx.z * P;

    const int m0 = blockIdx.y * 128, n0 = blockIdx.x * 128;
    const int tid = threadIdx.x;
    const int kf = tid >> 5, e4 = (tid & 31) * 4;
    const int warp = tid >> 5, lane = tid & 31;
    const int g = lane >> 2, t = lane & 3;
    const int wm = warp & 3, wn = warp >> 2;
    const int m0w = wm * 32, n0w = wn * 64;

    float acc[2][8][4];
    #pragma unroll
    for (int i = 0; i < 2; i++)
        #pragma unroll
        for (int j = 0; j < 8; j++)
            #pragma unroll
            for (int r = 0; r < 4; r++) acc[i][j][r] = 0.f;

    uint4 ra0, ra1, rb0, rb1;
    auto ld4A = [&](int krow, uint4& r) {
        const uint32_t* src = Ab + (size_t)krow * P;
        int m = m0 + e4;
        if (m + 3 < P) r = *(const uint4*)(src + m);
        else {
            r.x = (m+0 < P) ? src[m+0] : 0u;
            r.y = (m+1 < P) ? src[m+1] : 0u;
            r.z = (m+2 < P) ? src[m+2] : 0u;
            r.w = (m+3 < P) ? src[m+3] : 0u;
        }
    };
    auto ld4B = [&](int krow, uint4& r) {
        const uint32_t* src = Bb + (size_t)krow * D;
        int n = n0 + e4;
        if (n + 3 < D) r = *(const uint4*)(src + n);
        else {
            r.x = (n+0 < D) ? src[n+0] : 0u;
            r.y = (n+1 < D) ? src[n+1] : 0u;
            r.z = (n+2 < D) ? src[n+2] : 0u;
            r.w = (n+3 < D) ? src[n+3] : 0u;
        }
    };
    auto loadReg = [&](int k0) {
        ld4A(k0 + kf, ra0);
        ld4A(k0 + kf + 8, ra1);
        ld4B(k0 + kf, rb0);
        ld4B(k0 + kf + 8, rb1);
    };
    auto writeS = [&](int buf) {
        *(uint4*)&As[buf][kf][e4]   = ra0;
        *(uint4*)&As[buf][kf+8][e4] = ra1;
        *(uint4*)&Bs[buf][kf][e4]   = rb0;
        *(uint4*)&Bs[buf][kf+8][e4] = rb1;
    };

    loadReg(0);
    writeS(0);
    __syncthreads();

    int buf = 0;
    for (int k0 = 0; k0 < C; k0 += 16) {
        bool nxt = (k0 + 16) < C;
        if (nxt) loadReg(k0 + 16);

        #pragma unroll
        for (int ks = 0; ks < 2; ks++) {
            int kb = ks * 8;
            uint32_t af[2][4], bf[8][2];
            #pragma unroll
            for (int mt = 0; mt < 2; mt++) {
                int mb = m0w + mt * 16 + g;
                af[mt][0] = As[buf][kb + t][mb];
                af[mt][1] = As[buf][kb + t][mb + 8];
                af[mt][2] = As[buf][kb + t + 4][mb];
                af[mt][3] = As[buf][kb + t + 4][mb + 8];
            }
            #pragma unroll
            for (int nt = 0; nt < 8; nt++) {
                int nb = n0w + nt * 8 + g;
                bf[nt][0] = Bs[buf][kb + t][nb];
                bf[nt][1] = Bs[buf][kb + t + 4][nb];
            }
            #pragma unroll
            for (int mt = 0; mt < 2; mt++)
                #pragma unroll
                for (int nt = 0; nt < 8; nt++)
                    mma_tf32(acc[mt][nt][0], acc[mt][nt][1], acc[mt][nt][2], acc[mt][nt][3],
                             af[mt][0], af[mt][1], af[mt][2], af[mt][3],
                             bf[nt][0], bf[nt][1]);
        }

        if (nxt) {
            writeS(buf ^ 1);
            __syncthreads();
            buf ^= 1;
        }
    }

    #pragma unroll
    for (int mt = 0; mt < 2; mt++) {
        int gm = m0 + m0w + mt * 16 + g;
        float s0 = 0.f, s1 = 0.f;
        #pragma unroll
        for (int nt = 0; nt < 8; nt++) {
            int gn = n0 + n0w + nt * 8 + 2 * t;
            bool c0 = (gn < D), c1 = (gn + 1 < D);
            float e0 = __expf(acc[mt][nt][0]);
            float e1 = __expf(acc[mt][nt][1]);
            float e2 = __expf(acc[mt][nt][2]);
            float e3 = __expf(acc[mt][nt][3]);
            if (gm < P) {
                if (c0) Cb[(size_t)gm * D + gn]     = f2tf32(e0);
                if (c1) Cb[(size_t)gm * D + gn + 1] = f2tf32(e1);
            }
            if (gm + 8 < P) {
                if (c0) Cb[(size_t)(gm + 8) * D + gn]     = f2tf32(e2);
                if (c1) Cb[(size_t)(gm + 8) * D + gn + 1] = f2tf32(e3);
            }
            s0 += (c0 ? e0 : 0.f) + (c1 ? e1 : 0.f);
            s1 += (c0 ? e2 : 0.f) + (c1 ? e3 : 0.f);
        }
        s0 += __shfl_xor_sync(0xffffffff, s0, 1);
        s0 += __shfl_xor_sync(0xffffffff, s0, 2);
        s1 += __shfl_xor_sync(0xffffffff, s1, 1);
        s1 += __shfl_xor_sync(0xffffffff, s1, 2);
        if (t == 0) {
            if (gm < P)     atomicAdd(&rsb[gm], s0);
            if (gm + 8 < P) atomicAdd(&rsb[gm + 8], s1);
        }
    }
}

// -------- beff = b_h + W_h[:,2C:3C] @ v_c; v_c from constant c0 --------
__global__ void beff_k(const float* __restrict__ w_vc, const float* __restrict__ c0,
                       const float* __restrict__ w_h, const float* __restrict__ b_h,
                       float* __restrict__ beff)
{
    __shared__ float vc[C];
    int c = threadIdx.x;
    float s = 0.f;
    for (int ci = 0; ci < C; ci++) {
        float ws = 0.f;
        #pragma unroll
        for (int t = 0; t < 9; t++) ws += w_vc[((size_t)c * C + ci) * 9 + t];
        s += ws * c0[ci];
    }
    vc[c] = s;
    __syncthreads();
    float r = b_h[c];
    for (int j = 0; j < C; j++) r += w_h[(size_t)c * (3*C) + 2*C + j] * vc[j];
    beff[c] = r;
}

extern "C" void kernel_launch(void* const* d_in, const int* in_sizes, int n_in,
                              void* d_out, int out_size)
{
    const float* inp  = (const float*)d_in[0];
    const float* c0   = (const float*)d_in[1];
    const float* w_x  = (const float*)d_in[2];
    const float* b_x  = (const float*)d_in[3];
    const float* w_qx = (const float*)d_in[4];
    const float* w_kx = (const float*)d_in[6];
    const float* w_vx = (const float*)d_in[8];
    const float* w_vc = (const float*)d_in[9];
    const float* w_h  = (const float*)d_in[14];
    const float* b_h  = (const float*)d_in[15];
    const float* w_o  = (const float*)d_in[16];
    const float* b_o  = (const float*)d_in[17];
    float* out = (float*)d_out;

    uint32_t *xa, *q, *k, *v, *sc, *h;
    float *rs, *beff;
    cudaGetSymbolAddress((void**)&xa,   g_xa);
    cudaGetSymbolAddress((void**)&q,    g_q);
    cudaGetSymbolAddress((void**)&k,    g_k);
    cudaGetSymbolAddress((void**)&v,    g_v);
    cudaGetSymbolAddress((void**)&sc,   g_sc);
    cudaGetSymbolAddress((void**)&rs,   g_rs);
    cudaGetSymbolAddress((void**)&h,    g_h);
    cudaGetSymbolAddress((void**)&beff, g_beff);
    uint32_t *wx, *wh, *wo;
    cudaGetSymbolAddress((void**)&wx, g_wx);
    cudaGetSymbolAddress((void**)&wh, g_wh);
    cudaGetSymbolAddress((void**)&wo, g_wo);

    const int NT_P = (P + 63) / 64;      // 21

    // constants and weight pre-conversion (+ transposed qkv weights)
    beff_k<<<1, C>>>(w_vc, c0, w_h, b_h, beff);
    preconv_k<<<(C*3*C + 255)/256, 256>>>(w_x, w_h, w_o);
    preconv_t_k<<<(KC*C + 255)/256, 256>>>(w_qx, w_kx, w_vx);
    zero_rs_k<<<(NB*P + 255)/256, 256>>>();

    // x = W_x @ inp + b_x -> g_xa rows [0,128) as tf32 bits
    gemm64t_k<0,1,false,true><<<dim3(NT_P, 2, NB), 128>>>(
        wx, 0, C, inp, (size_t)C*P, P, xa, (size_t)2*C*P, P, P, C, b_x, 0);

    // q/k/v 3x3 convs, tf32 MMA mega-launch (coalesced transposed weights)
    qkv_mega_k<<<dim3(62, 1, NB), 128>>>(xa, q, k, v);

    // ex[p,d] = exp(q^T k) + row sums (fused)
    gemm_big_k<<<dim3((D + 127)/128, (P + 127)/128, NB), 256>>>(q, k, sc, rs);

    // a0[c,p] = (v @ ex^T)[c,p] / rs[p]  (R11-proven 64x64 PV)
    gemm64t_k<1,3,true,true><<<dim3(NT_P, 2, NB), 128>>>(
        v, (size_t)C*D, D, sc, (size_t)P*D, D, xa + (size_t)C*P, (size_t)2*C*P, P,
        P, D, rs, P);

    // h = tanh(W_h[:, :2C] @ [x; a0] + beff)
    gemm64t_k<0,2,true,true><<<dim3(NT_P, 2, NB), 128>>>(
        wh, 0, 3*C, xa, (size_t)2*C*P, P, h, (size_t)C*P, P, P, 2*C, beff, 0);

    // out = W_o @ h + b_o  (fp32 output)
    gemm64t_k<0,1,true,false><<<dim3(NT_P, 2, NB), 128>>>(
        wo, 0, C, h, (size_t)C*P, P, out, (size_t)C*P, P, P, C, b_o, 0);
}

// round 15
// speedup vs baseline: 1.1755x; 1.0096x over previous
#include <cuda_runtime.h>
#include <cstdint>
#include <cstddef>

// Problem dims
#define NB 8
#define C 128
#define HH 36
#define WW 36
#define P (HH*WW)          // 1296 query tokens
#define HV 34
#define WV 34
#define D (HV*WV)          // 1156 key/value tokens
#define KC (C*9)           // 1152 im2col K

// -------- scratch (static device memory; no allocation APIs) --------
__device__ uint32_t g_xa[(size_t)NB*2*C*P];   // rows 0..127: x, rows 128..255: a0
__device__ uint32_t g_q[(size_t)NB*C*P];
__device__ uint32_t g_k[(size_t)NB*C*D];
__device__ uint32_t g_v[(size_t)NB*C*D];
__device__ uint32_t g_sc[(size_t)NB*(size_t)P*D]; // exp(scores) tf32 bits
__device__ float    g_rs[(size_t)NB*P];           // row sums of exp
__device__ uint32_t g_h[(size_t)NB*C*P];
__device__ float    g_beff[C];
__device__ uint32_t g_wx[C*C];
__device__ uint32_t g_wh[C*3*C];
__device__ uint32_t g_wo[C*C];
// qkv weights pre-transposed to [kg][m], kg = t*128 + ci (t-major K order)
__device__ uint32_t g_wqt[KC*C];
__device__ uint32_t g_wkt[KC*C];
__device__ uint32_t g_wvt[KC*C];

// -------- tf32 helpers --------
__device__ __forceinline__ uint32_t f2tf32(float f) {
    uint32_t u;
    asm("cvt.rna.tf32.f32 %0, %1;" : "=r"(u) : "f"(f));
    return u;
}

__device__ __forceinline__ void mma_tf32(
    float& c0, float& c1, float& c2, float& c3,
    uint32_t a0, uint32_t a1, uint32_t a2, uint32_t a3,
    uint32_t b0, uint32_t b1)
{
    asm volatile(
        "mma.sync.aligned.m16n8k8.row.col.f32.tf32.tf32.f32 "
        "{%0,%1,%2,%3}, {%4,%5,%6,%7}, {%8,%9}, {%0,%1,%2,%3};"
        : "+f"(c0), "+f"(c1), "+f"(c2), "+f"(c3)
        : "r"(a0), "r"(a1), "r"(a2), "r"(a3), "r"(b0), "r"(b1));
}

// -------- weight pre-conversion --------
__global__ void preconv_k(const float* __restrict__ wx, const float* __restrict__ wh,
                          const float* __restrict__ wo)
{
    int i = blockIdx.x * 256 + threadIdx.x;
    if (i < C*C)   { g_wx[i] = f2tf32(wx[i]); g_wo[i] = f2tf32(wo[i]); }
    if (i < C*3*C) g_wh[i] = f2tf32(wh[i]);
}

// transpose qkv weights: g_w?t[kg*C + m] = w?[m][ci][t], kg = t*128 + ci
// also zeroes g_rs (piggyback; KC*C threads >> NB*P)
__global__ void preconv_t_k(const float* __restrict__ wq, const float* __restrict__ wk,
                            const float* __restrict__ wv)
{
    int i = blockIdx.x * 256 + threadIdx.x;
    if (i < NB * P) g_rs[i] = 0.f;
    if (i >= KC * C) return;
    int kg = i / C, m = i % C;
    int t = kg >> 7, ci = kg & 127;
    size_t src = ((size_t)m * C + ci) * 9 + t;
    g_wqt[i] = f2tf32(wq[src]);
    g_wkt[i] = f2tf32(wk[src]);
    g_wvt[i] = f2tf32(wv[src]);
}

// ============================================================
// qkv_mega: all three 3x3 conv GEMMs in ONE launch, tf32 MMA core.
// CTA tile 64(m) x 128(n), 128 threads = 4 warps, warp tile 32x64.
// BK = 32 (4 k8 sub-steps per sync interval).
// A read COALESCED from pre-transposed [kg][m] weights.
// ============================================================
__global__ void __launch_bounds__(128) qkv_mega_k(
    const uint32_t* __restrict__ xa,
    uint32_t* __restrict__ qo, uint32_t* __restrict__ ko, uint32_t* __restrict__ vo)
{
    __shared__ uint32_t As[2][32][72];
    __shared__ uint32_t Bs[2][32][136];

    const int bz = blockIdx.z;
    const int tile = blockIdx.x;
    bool qmode; int my, nx;
    if (tile < 22) { qmode = true;  my = tile / 11; nx = tile % 11; }
    else { int t2 = tile - 22; qmode = false; my = t2 / 10; nx = t2 % 10; }

    const uint32_t* At = qmode ? g_wqt : ((my < 2) ? g_wkt : g_wvt);
    const int m0 = qmode ? my * 64 : (my & 1) * 64;
    const int Nn = qmode ? P : D;
    uint32_t* Cp = qmode ? (qo + (size_t)bz * C * P)
                         : ((my < 2) ? ko : vo) + (size_t)bz * C * D;
    const uint32_t* B = xa + (size_t)bz * 2 * C * P;
    const int n0 = nx * 128;
    const int ldc = Nn;

    const int tid = threadIdx.x;
    const int warp = tid >> 5, lane = tid & 31;
    const int g = lane >> 2, t = lane & 3;
    const int wm = warp & 1, wn = warp >> 1;
    const int m0w = wm * 32, n0w = wn * 64;

    // A loader: coalesced. kA = tid>>3 (rows kA, kA+16), mA0 = (tid&7)*8.
    const int kA = tid >> 3;
    const int mA0 = (tid & 7) * 8;

    int p = n0 + tid;
    bool npred; int iy, ix;
    if (qmode) { npred = (p < P); if (p >= P) p = 0; iy = p / WW; ix = p % WW; }
    else       { npred = (p < D); if (p >= D) p = 0; iy = p / WV; ix = p % WV; }

    float acc[2][8][4];
    #pragma unroll
    for (int i = 0; i < 2; i++)
        #pragma unroll
        for (int j = 0; j < 8; j++)
            #pragma unroll
            for (int r = 0; r < 4; r++) acc[i][j][r] = 0.f;

    uint4 ra4[4];
    uint32_t rb[32];

    auto loadAB = [&](int k0) {
        #pragma unroll
        for (int h = 0; h < 2; h++) {
            const uint32_t* arow = At + (size_t)(k0 + kA + 16 * h) * C + m0 + mA0;
            ra4[2*h]   = *(const uint4*)(arow);
            ra4[2*h+1] = *(const uint4*)(arow + 4);
        }
        int tt = k0 >> 7;                 // constant within 32-chunk (cb+31<=127)
        int ky = tt / 3, kx = tt - ky * 3;
        int cb = k0 & 127;
        if (qmode) {
            int sy = iy + ky - 1, sx = ix + kx - 1;
            bool pr = npred && sy >= 0 && sy < HH && sx >= 0 && sx < WW;
            int rowb = sy * WW + sx;
            #pragma unroll
            for (int i = 0; i < 32; i++)
                rb[i] = pr ? B[(size_t)(cb + i) * P + rowb] : 0u;
        } else {
            int rowb = (iy + ky) * WW + (ix + kx);
            #pragma unroll
            for (int i = 0; i < 32; i++)
                rb[i] = npred ? B[(size_t)(cb + i) * P + rowb] : 0u;
        }
    };

    auto writeS = [&](int buf) {
        *(uint4*)&As[buf][kA][mA0]          = ra4[0];
        *(uint4*)&As[buf][kA][mA0 + 4]      = ra4[1];
        *(uint4*)&As[buf][kA + 16][mA0]     = ra4[2];
        *(uint4*)&As[buf][kA + 16][mA0 + 4] = ra4[3];
        #pragma unroll
        for (int i = 0; i < 32; i++) Bs[buf][i][tid] = rb[i];
    };

    loadAB(0);
    writeS(0);
    __syncthreads();

    int buf = 0;
    for (int k0 = 0; k0 < KC; k0 += 32) {
        bool nxt = (k0 + 32) < KC;
        if (nxt) loadAB(k0 + 32);

        #pragma unroll
        for (int ks = 0; ks < 4; ks++) {
            int kb = ks * 8;
            uint32_t af[2][4], bf[8][2];
            #pragma unroll
            for (int mt = 0; mt < 2; mt++) {
                int mb = m0w + mt * 16 + g;
                af[mt][0] = As[buf][kb + t][mb];
                af[mt][1] = As[buf][kb + t][mb + 8];
                af[mt][2] = As[buf][kb + t + 4][mb];
                af[mt][3] = As[buf][kb + t + 4][mb + 8];
            }
            #pragma unroll
            for (int nt = 0; nt < 8; nt++) {
                int nb = n0w + nt * 8 + g;
                bf[nt][0] = Bs[buf][kb + t][nb];
                bf[nt][1] = Bs[buf][kb + t + 4][nb];
            }
            #pragma unroll
            for (int mt = 0; mt < 2; mt++)
                #pragma unroll
                for (int nt = 0; nt < 8; nt++)
                    mma_tf32(acc[mt][nt][0], acc[mt][nt][1], acc[mt][nt][2], acc[mt][nt][3],
                             af[mt][0], af[mt][1], af[mt][2], af[mt][3],
                             bf[nt][0], bf[nt][1]);
        }

        if (nxt) {
            writeS(buf ^ 1);
            __syncthreads();
            buf ^= 1;
        }
    }

    #pragma unroll
    for (int mt = 0; mt < 2; mt++) {
        int gm = m0 + m0w + mt * 16 + g;
        #pragma unroll
        for (int nt = 0; nt < 8; nt++) {
            int gn = n0 + n0w + nt * 8 + 2 * t;
            if (gn < Nn)     Cp[(size_t)gm * ldc + gn]           = f2tf32(acc[mt][nt][0]);
            if (gn + 1 < Nn) Cp[(size_t)gm * ldc + gn + 1]       = f2tf32(acc[mt][nt][1]);
            if (gn < Nn)     Cp[(size_t)(gm + 8) * ldc + gn]     = f2tf32(acc[mt][nt][2]);
            if (gn + 1 < Nn) Cp[(size_t)(gm + 8) * ldc + gn + 1] = f2tf32(acc[mt][nt][3]);
        }
    }
}

// ============================================================
// gemm64t: tf32 MMA 64x64 GEMM (R11-proven; short-K GEMMs + PV).
// BMODE: 0 = B plain [K][N], 1 = B transposed [N][K].
// BRAW: B already tf32 bits vs fp32. EPI: 0/1 bias/2 tanh/3 colscale.
// OU32: write tf32 bits vs fp32.
// ============================================================
template<int BMODE, int EPI, bool BRAW, bool OU32>
__global__ void __launch_bounds__(128) gemm64t_k(
    const uint32_t* __restrict__ A, size_t sA, int lda,
    const void* __restrict__ Bv, size_t sB, int ldb,
    void* __restrict__ Cv, size_t sC, int ldc,
    int N, int K,
    const float* __restrict__ aux, size_t sAux)
{
    __shared__ uint32_t As[2][16][72];
    __shared__ uint32_t Bs[2][16][72];
    A += (size_t)blockIdx.z * sA;
    const uint32_t* B32 = (const uint32_t*)Bv + (BRAW ? (size_t)blockIdx.z * sB : 0);
    const float*    Bf  = (const float*)Bv    + (BRAW ? 0 : (size_t)blockIdx.z * sB);
    uint32_t* C32 = (uint32_t*)Cv + (size_t)blockIdx.z * sC;
    float*    Cf  = (float*)Cv    + (size_t)blockIdx.z * sC;
    const float* auxp = aux + (size_t)blockIdx.z * sAux;

    const int m0 = blockIdx.y * 64, n0 = blockIdx.x * 64;
    const int tid = threadIdx.x;
    const int warp = tid >> 5, lane = tid & 31;
    const int g = lane >> 2, t = lane & 3;
    const int wm = warp & 1, wn = warp >> 1;
    const int m0w = wm * 32, n0w = wn * 32;

    const int ka = tid & 15;
    const int ma = tid >> 4;
    const int nb64 = tid & 63;
    const int kb2 = tid >> 6;
    const int kb16 = tid & 15;

    float acc[2][4][4];
    #pragma unroll
    for (int i = 0; i < 2; i++)
        #pragma unroll
        for (int j = 0; j < 4; j++)
            #pragma unroll
            for (int r = 0; r < 4; r++) acc[i][j][r] = 0.f;

    uint32_t ra[8], rb[8];

    auto ldB = [&](int gk, int gn) -> uint32_t {
        if (gn >= N || gk >= K) return 0u;
        if (BRAW) return B32[(size_t)(BMODE == 1 ? gn : gk) * ldb + (BMODE == 1 ? gk : gn)];
        else      return f2tf32(Bf[(size_t)(BMODE == 1 ? gn : gk) * ldb + (BMODE == 1 ? gk : gn)]);
    };

    auto loadAB = [&](int k0) {
        #pragma unroll
        for (int i = 0; i < 8; i++) {
            int gk = k0 + ka;
            int m = m0 + ma + 8 * i;
            ra[i] = (gk < K) ? A[(size_t)m * lda + gk] : 0u;
        }
        if (BMODE == 0) {
            #pragma unroll
            for (int i = 0; i < 8; i++)
                rb[i] = ldB(k0 + kb2 + 2 * i, n0 + nb64);
        } else {
            #pragma unroll
            for (int i = 0; i < 8; i++)
                rb[i] = ldB(k0 + kb16, n0 + (tid >> 4) + 8 * i);
        }
    };

    auto writeS = [&](int buf) {
        #pragma unroll
        for (int i = 0; i < 8; i++) As[buf][ka][ma + 8 * i] = ra[i];
        if (BMODE == 1) {
            #pragma unroll
            for (int i = 0; i < 8; i++) Bs[buf][kb16][(tid >> 4) + 8 * i] = rb[i];
        } else {
            #pragma unroll
            for (int i = 0; i < 8; i++) Bs[buf][kb2 + 2 * i][nb64] = rb[i];
        }
    };

    loadAB(0);
    writeS(0);
    __syncthreads();

    int buf = 0;
    for (int k0 = 0; k0 < K; k0 += 16) {
        bool nxt = (k0 + 16) < K;
        if (nxt) loadAB(k0 + 16);

        #pragma unroll
        for (int ks = 0; ks < 2; ks++) {
            int kb = ks * 8;
            uint32_t af[2][4], bf[4][2];
            #pragma unroll
            for (int mt = 0; mt < 2; mt++) {
                int mb = m0w + mt * 16 + g;
                af[mt][0] = As[buf][kb + t][mb];
                af[mt][1] = As[buf][kb + t][mb + 8];
                af[mt][2] = As[buf][kb + t + 4][mb];
                af[mt][3] = As[buf][kb + t + 4][mb + 8];
            }
            #pragma unroll
            for (int nt = 0; nt < 4; nt++) {
                int nb = n0w + nt * 8 + g;
                bf[nt][0] = Bs[buf][kb + t][nb];
                bf[nt][1] = Bs[buf][kb + t + 4][nb];
            }
            #pragma unroll
            for (int mt = 0; mt < 2; mt++)
                #pragma unroll
                for (int nt = 0; nt < 4; nt++)
                    mma_tf32(acc[mt][nt][0], acc[mt][nt][1], acc[mt][nt][2], acc[mt][nt][3],
                             af[mt][0], af[mt][1], af[mt][2], af[mt][3],
                             bf[nt][0], bf[nt][1]);
        }

        if (nxt) {
            writeS(buf ^ 1);
            __syncthreads();
            buf ^= 1;
        }
    }

    #pragma unroll
    for (int mt = 0; mt < 2; mt++) {
        int gm = m0 + m0w + mt * 16 + g;
        float bv0 = (EPI == 1 || EPI == 2) ? auxp[gm] : 0.f;
        float bv8 = (EPI == 1 || EPI == 2) ? auxp[gm + 8] : 0.f;
        #pragma unroll
        for (int nt = 0; nt < 4; nt++) {
            int gn = n0 + n0w + nt * 8 + 2 * t;
            float v0 = acc[mt][nt][0], v1 = acc[mt][nt][1];
            float v2 = acc[mt][nt][2], v3 = acc[mt][nt][3];
            if (EPI == 1) { v0 += bv0; v1 += bv0; v2 += bv8; v3 += bv8; }
            if (EPI == 2) {
                v0 = tanhf(v0 + bv0); v1 = tanhf(v1 + bv0);
                v2 = tanhf(v2 + bv8); v3 = tanhf(v3 + bv8);
            }
            if (EPI == 3) {
                float i0 = (gn < N)     ? 1.f / auxp[gn]     : 0.f;
                float i1 = (gn + 1 < N) ? 1.f / auxp[gn + 1] : 0.f;
                v0 *= i0; v1 *= i1; v2 *= i0; v3 *= i1;
            }
            if (OU32) {
                if (gn < N)     C32[(size_t)gm * ldc + gn]           = f2tf32(v0);
                if (gn + 1 < N) C32[(size_t)gm * ldc + gn + 1]       = f2tf32(v1);
                if (gn < N)     C32[(size_t)(gm + 8) * ldc + gn]     = f2tf32(v2);
                if (gn + 1 < N) C32[(size_t)(gm + 8) * ldc + gn + 1] = f2tf32(v3);
            } else {
                if (gn < N)     Cf[(size_t)gm * ldc + gn]           = v0;
                if (gn + 1 < N) Cf[(size_t)gm * ldc + gn + 1]       = v1;
                if (gn < N)     Cf[(size_t)(gm + 8) * ldc + gn]     = v2;
                if (gn + 1 < N) Cf[(size_t)(gm + 8) * ldc + gn + 1] = v3;
            }
        }
    }
}

// ============================================================
// gemm_big: exp-scores + row sums. tf32 MMA, BK=16.
// ============================================================
__global__ void __launch_bounds__(256) gemm_big_k(
    const uint32_t* __restrict__ Aq,
    const uint32_t* __restrict__ Bk,
    uint32_t* __restrict__ Cs,
    float* __restrict__ rs)
{
    __shared__ uint32_t As[2][16][136];
    __shared__ uint32_t Bs[2][16][136];
    const uint32_t* Ab = Aq + (size_t)blockIdx.z * C * P;
    const uint32_t* Bb = Bk + (size_t)blockIdx.z * C * D;
    uint32_t* Cb = Cs + (size_t)blockIdx.z * (size_t)P * D;
    float* rsb = rs + (size_t)blockIdx.z * P;

    const int m0 = blockIdx.y * 128, n0 = blockIdx.x * 128;
    const int tid = threadIdx.x;
    const int kf = tid >> 5, e4 = (tid & 31) * 4;
    const int warp = tid >> 5, lane = tid & 31;
    const int g = lane >> 2, t = lane & 3;
    const int wm = warp & 3, wn = warp >> 2;
    const int m0w = wm * 32, n0w = wn * 64;

    float acc[2][8][4];
    #pragma unroll
    for (int i = 0; i < 2; i++)
        #pragma unroll
        for (int j = 0; j < 8; j++)
            #pragma unroll
            for (int r = 0; r < 4; r++) acc[i][j][r] = 0.f;

    uint4 ra0, ra1, rb0, rb1;
    auto ld4A = [&](int krow, uint4& r) {
        const uint32_t* src = Ab + (size_t)krow * P;
        int m = m0 + e4;
        if (m + 3 < P) r = *(const uint4*)(src + m);
        else {
            r.x = (m+0 < P) ? src[m+0] : 0u;
            r.y = (m+1 < P) ? src[m+1] : 0u;
            r.z = (m+2 < P) ? src[m+2] : 0u;
            r.w = (m+3 < P) ? src[m+3] : 0u;
        }
    };
    auto ld4B = [&](int krow, uint4& r) {
        const uint32_t* src = Bb + (size_t)krow * D;
        int n = n0 + e4;
        if (n + 3 < D) r = *(const uint4*)(src + n);
        else {
            r.x = (n+0 < D) ? src[n+0] : 0u;
            r.y = (n+1 < D) ? src[n+1] : 0u;
            r.z = (n+2 < D) ? src[n+2] : 0u;
            r.w = (n+3 < D) ? src[n+3] : 0u;
        }
    };
    auto loadReg = [&](int k0) {
        ld4A(k0 + kf, ra0);
        ld4A(k0 + kf + 8, ra1);
        ld4B(k0 + kf, rb0);
        ld4B(k0 + kf + 8, rb1);
    };
    auto writeS = [&](int buf) {
        *(uint4*)&As[buf][kf][e4]   = ra0;
        *(uint4*)&As[buf][kf+8][e4] = ra1;
        *(uint4*)&Bs[buf][kf][e4]   = rb0;
        *(uint4*)&Bs[buf][kf+8][e4] = rb1;
    };

    loadReg(0);
    writeS(0);
    __syncthreads();

    int buf = 0;
    for (int k0 = 0; k0 < C; k0 += 16) {
        bool nxt = (k0 + 16) < C;
        if (nxt) loadReg(k0 + 16);

        #pragma unroll
        for (int ks = 0; ks < 2; ks++) {
            int kb = ks * 8;
            uint32_t af[2][4], bf[8][2];
            #pragma unroll
            for (int mt = 0; mt < 2; mt++) {
                int mb = m0w + mt * 16 + g;
                af[mt][0] = As[buf][kb + t][mb];
                af[mt][1] = As[buf][kb + t][mb + 8];
                af[mt][2] = As[buf][kb + t + 4][mb];
                af[mt][3] = As[buf][kb + t + 4][mb + 8];
            }
            #pragma unroll
            for (int nt = 0; nt < 8; nt++) {
                int nb = n0w + nt * 8 + g;
                bf[nt][0] = Bs[buf][kb + t][nb];
                bf[nt][1] = Bs[buf][kb + t + 4][nb];
            }
            #pragma unroll
            for (int mt = 0; mt < 2; mt++)
                #pragma unroll
                for (int nt = 0; nt < 8; nt++)
                    mma_tf32(acc[mt][nt][0], acc[mt][nt][1], acc[mt][nt][2], acc[mt][nt][3],
                             af[mt][0], af[mt][1], af[mt][2], af[mt][3],
                             bf[nt][0], bf[nt][1]);
        }

        if (nxt) {
            writeS(buf ^ 1);
            __syncthreads();
            buf ^= 1;
        }
    }

    #pragma unroll
    for (int mt = 0; mt < 2; mt++) {
        int gm = m0 + m0w + mt * 16 + g;
        float s0 = 0.f, s1 = 0.f;
        #pragma unroll
        for (int nt = 0; nt < 8; nt++) {
            int gn = n0 + n0w + nt * 8 + 2 * t;
            bool c0 = (gn < D), c1 = (gn + 1 < D);
            float e0 = __expf(acc[mt][nt][0]);
            float e1 = __expf(acc[mt][nt][1]);
            float e2 = __expf(acc[mt][nt][2]);
            float e3 = __expf(acc[mt][nt][3]);
            if (gm < P) {
                if (c0) Cb[(size_t)gm * D + gn]     = f2tf32(e0);
                if (c1) Cb[(size_t)gm * D + gn + 1] = f2tf32(e1);
            }
            if (gm + 8 < P) {
                if (c0) Cb[(size_t)(gm + 8) * D + gn]     = f2tf32(e2);
                if (c1) Cb[(size_t)(gm + 8) * D + gn + 1] = f2tf32(e3);
            }
            s0 += (c0 ? e0 : 0.f) + (c1 ? e1 : 0.f);
            s1 += (c0 ? e2 : 0.f) + (c1 ? e3 : 0.f);
        }
        s0 += __shfl_xor_sync(0xffffffff, s0, 1);
        s0 += __shfl_xor_sync(0xffffffff, s0, 2);
        s1 += __shfl_xor_sync(0xffffffff, s1, 1);
        s1 += __shfl_xor_sync(0xffffffff, s1, 2);
        if (t == 0) {
            if (gm < P)     atomicAdd(&rsb[gm], s0);
            if (gm + 8 < P) atomicAdd(&rsb[gm + 8], s1);
        }
    }
}

// -------- beff = b_h + W_h[:,2C:3C] @ v_c; v_c from constant c0 --------
__global__ void beff_k(const float* __restrict__ w_vc, const float* __restrict__ c0,
                       const float* __restrict__ w_h, const float* __restrict__ b_h,
                       float* __restrict__ beff)
{
    __shared__ float vc[C];
    int c = threadIdx.x;
    float s = 0.f;
    for (int ci = 0; ci < C; ci++) {
        float ws = 0.f;
        #pragma unroll
        for (int t = 0; t < 9; t++) ws += w_vc[((size_t)c * C + ci) * 9 + t];
        s += ws * c0[ci];
    }
    vc[c] = s;
    __syncthreads();
    float r = b_h[c];
    for (int j = 0; j < C; j++) r += w_h[(size_t)c * (3*C) + 2*C + j] * vc[j];
    beff[c] = r;
}

extern "C" void kernel_launch(void* const* d_in, const int* in_sizes, int n_in,
                              void* d_out, int out_size)
{
    const float* inp  = (const float*)d_in[0];
    const float* c0   = (const float*)d_in[1];
    const float* w_x  = (const float*)d_in[2];
    const float* b_x  = (const float*)d_in[3];
    const float* w_qx = (const float*)d_in[4];
    const float* w_kx = (const float*)d_in[6];
    const float* w_vx = (const float*)d_in[8];
    const float* w_vc = (const float*)d_in[9];
    const float* w_h  = (const float*)d_in[14];
    const float* b_h  = (const float*)d_in[15];
    const float* w_o  = (const float*)d_in[16];
    const float* b_o  = (const float*)d_in[17];
    float* out = (float*)d_out;

    uint32_t *xa, *q, *k, *v, *sc, *h;
    float *rs, *beff;
    cudaGetSymbolAddress((void**)&xa,   g_xa);
    cudaGetSymbolAddress((void**)&q,    g_q);
    cudaGetSymbolAddress((void**)&k,    g_k);
    cudaGetSymbolAddress((void**)&v,    g_v);
    cudaGetSymbolAddress((void**)&sc,   g_sc);
    cudaGetSymbolAddress((void**)&rs,   g_rs);
    cudaGetSymbolAddress((void**)&h,    g_h);
    cudaGetSymbolAddress((void**)&beff, g_beff);
    uint32_t *wx, *wh, *wo;
    cudaGetSymbolAddress((void**)&wx, g_wx);
    cudaGetSymbolAddress((void**)&wh, g_wh);
    cudaGetSymbolAddress((void**)&wo, g_wo);

    const int NT_P = (P + 63) / 64;      // 21

    // constants and weight pre-conversion (+ transposed qkv weights, rs zero)
    beff_k<<<1, C>>>(w_vc, c0, w_h, b_h, beff);
    preconv_k<<<(C*3*C + 255)/256, 256>>>(w_x, w_h, w_o);
    preconv_t_k<<<(KC*C + 255)/256, 256>>>(w_qx, w_kx, w_vx);

    // x = W_x @ inp + b_x -> g_xa rows [0,128) as tf32 bits
    gemm64t_k<0,1,false,true><<<dim3(NT_P, 2, NB), 128>>>(
        wx, 0, C, inp, (size_t)C*P, P, xa, (size_t)2*C*P, P, P, C, b_x, 0);

    // q/k/v 3x3 convs, tf32 MMA mega-launch (BK=32, coalesced weights)
    qkv_mega_k<<<dim3(62, 1, NB), 128>>>(xa, q, k, v);

    // ex[p,d] = exp(q^T k) + row sums (fused)
    gemm_big_k<<<dim3((D + 127)/128, (P + 127)/128, NB), 256>>>(q, k, sc, rs);

    // a0[c,p] = (v @ ex^T)[c,p] / rs[p]
    gemm64t_k<1,3,true,true><<<dim3(NT_P, 2, NB), 128>>>(
        v, (size_t)C*D, D, sc, (size_t)P*D, D, xa + (size_t)C*P, (size_t)2*C*P, P,
        P, D, rs, P);

    // h = tanh(W_h[:, :2C] @ [x; a0] + beff)
    gemm64t_k<0,2,true,true><<<dim3(NT_P, 2, NB), 128>>>(
        wh, 0, 3*C, xa, (size_t)2*C*P, P, h, (size_t)C*P, P, P, 2*C, beff, 0);

    // out = W_o @ h + b_o  (fp32 output)
    gemm64t_k<0,1,true,false><<<dim3(NT_P, 2, NB), 128>>>(
        wo, 0, C, h, (size_t)C*P, P, out, (size_t)C*P, P, P, C, b_o, 0);
}

// round 16
// speedup vs baseline: 1.1770x; 1.0012x over previous
#include <cuda_runtime.h>
#include <cstdint>
#include <cstddef>

// Problem dims
#define NB 8
#define C 128
#define HH 36
#define WW 36
#define P (HH*WW)          // 1296 query tokens
#define HV 34
#define WV 34
#define D (HV*WV)          // 1156 key/value tokens
#define KC (C*9)           // 1152 im2col K

// -------- scratch (static device memory; no allocation APIs) --------
__device__ uint32_t g_xa[(size_t)NB*2*C*P];   // rows 0..127: x, rows 128..255: a0
__device__ uint32_t g_q[(size_t)NB*C*P];
__device__ uint32_t g_k[(size_t)NB*C*D];
__device__ uint32_t g_v[(size_t)NB*C*D];
__device__ uint32_t g_sc[(size_t)NB*(size_t)P*D]; // exp(scores) tf32 bits
__device__ float    g_rs[(size_t)NB*P];           // row sums of exp
__device__ float    g_beff[C];
__device__ uint32_t g_wx[C*C];
__device__ uint32_t g_wh[C*3*C];
__device__ uint32_t g_wo[C*C];
// qkv weights pre-transposed to [kg][m], kg = t*128 + ci (t-major K order)
__device__ uint32_t g_wqt[KC*C];
__device__ uint32_t g_wkt[KC*C];
__device__ uint32_t g_wvt[KC*C];

// -------- tf32 helpers --------
__device__ __forceinline__ uint32_t f2tf32(float f) {
    uint32_t u;
    asm("cvt.rna.tf32.f32 %0, %1;" : "=r"(u) : "f"(f));
    return u;
}

__device__ __forceinline__ void mma_tf32(
    float& c0, float& c1, float& c2, float& c3,
    uint32_t a0, uint32_t a1, uint32_t a2, uint32_t a3,
    uint32_t b0, uint32_t b1)
{
    asm volatile(
        "mma.sync.aligned.m16n8k8.row.col.f32.tf32.tf32.f32 "
        "{%0,%1,%2,%3}, {%4,%5,%6,%7}, {%8,%9}, {%0,%1,%2,%3};"
        : "+f"(c0), "+f"(c1), "+f"(c2), "+f"(c3)
        : "r"(a0), "r"(a1), "r"(a2), "r"(a3), "r"(b0), "r"(b1));
}

// -------- merged weight pre-conversion (one launch) --------
// covers: wx/wo (C*C), wh (C*3C), qkv transpose (KC*C), rs zero (NB*P)
__global__ void preconv_all_k(const float* __restrict__ wx, const float* __restrict__ wh,
                              const float* __restrict__ wo,
                              const float* __restrict__ wq, const float* __restrict__ wk,
                              const float* __restrict__ wv)
{
    int i = blockIdx.x * 256 + threadIdx.x;
    if (i < NB * P) g_rs[i] = 0.f;
    if (i < C*C)   { g_wx[i] = f2tf32(wx[i]); g_wo[i] = f2tf32(wo[i]); }
    if (i < C*3*C) g_wh[i] = f2tf32(wh[i]);
    if (i < KC * C) {
        int kg = i / C, m = i % C;
        int t = kg >> 7, ci = kg & 127;
        size_t src = ((size_t)m * C + ci) * 9 + t;
        g_wqt[i] = f2tf32(wq[src]);
        g_wkt[i] = f2tf32(wk[src]);
        g_wvt[i] = f2tf32(wv[src]);
    }
}

// ============================================================
// qkv_mega: all three 3x3 conv GEMMs in ONE launch, tf32 MMA core.
// CTA tile 64(m) x 128(n), 128 threads, BK = 32, coalesced A.
// ============================================================
__global__ void __launch_bounds__(128) qkv_mega_k(
    const uint32_t* __restrict__ xa,
    uint32_t* __restrict__ qo, uint32_t* __restrict__ ko, uint32_t* __restrict__ vo)
{
    __shared__ uint32_t As[2][32][72];
    __shared__ uint32_t Bs[2][32][136];

    const int bz = blockIdx.z;
    const int tile = blockIdx.x;
    bool qmode; int my, nx;
    if (tile < 22) { qmode = true;  my = tile / 11; nx = tile % 11; }
    else { int t2 = tile - 22; qmode = false; my = t2 / 10; nx = t2 % 10; }

    const uint32_t* At = qmode ? g_wqt : ((my < 2) ? g_wkt : g_wvt);
    const int m0 = qmode ? my * 64 : (my & 1) * 64;
    const int Nn = qmode ? P : D;
    uint32_t* Cp = qmode ? (qo + (size_t)bz * C * P)
                         : ((my < 2) ? ko : vo) + (size_t)bz * C * D;
    const uint32_t* B = xa + (size_t)bz * 2 * C * P;
    const int n0 = nx * 128;
    const int ldc = Nn;

    const int tid = threadIdx.x;
    const int warp = tid >> 5, lane = tid & 31;
    const int g = lane >> 2, t = lane & 3;
    const int wm = warp & 1, wn = warp >> 1;
    const int m0w = wm * 32, n0w = wn * 64;

    const int kA = tid >> 3;
    const int mA0 = (tid & 7) * 8;

    int p = n0 + tid;
    bool npred; int iy, ix;
    if (qmode) { npred = (p < P); if (p >= P) p = 0; iy = p / WW; ix = p % WW; }
    else       { npred = (p < D); if (p >= D) p = 0; iy = p / WV; ix = p % WV; }

    float acc[2][8][4];
    #pragma unroll
    for (int i = 0; i < 2; i++)
        #pragma unroll
        for (int j = 0; j < 8; j++)
            #pragma unroll
            for (int r = 0; r < 4; r++) acc[i][j][r] = 0.f;

    uint4 ra4[4];
    uint32_t rb[32];

    auto loadAB = [&](int k0) {
        #pragma unroll
        for (int h = 0; h < 2; h++) {
            const uint32_t* arow = At + (size_t)(k0 + kA + 16 * h) * C + m0 + mA0;
            ra4[2*h]   = *(const uint4*)(arow);
            ra4[2*h+1] = *(const uint4*)(arow + 4);
        }
        int tt = k0 >> 7;
        int ky = tt / 3, kx = tt - ky * 3;
        int cb = k0 & 127;
        if (qmode) {
            int sy = iy + ky - 1, sx = ix + kx - 1;
            bool pr = npred && sy >= 0 && sy < HH && sx >= 0 && sx < WW;
            int rowb = sy * WW + sx;
            #pragma unroll
            for (int i = 0; i < 32; i++)
                rb[i] = pr ? B[(size_t)(cb + i) * P + rowb] : 0u;
        } else {
            int rowb = (iy + ky) * WW + (ix + kx);
            #pragma unroll
            for (int i = 0; i < 32; i++)
                rb[i] = npred ? B[(size_t)(cb + i) * P + rowb] : 0u;
        }
    };

    auto writeS = [&](int buf) {
        *(uint4*)&As[buf][kA][mA0]          = ra4[0];
        *(uint4*)&As[buf][kA][mA0 + 4]      = ra4[1];
        *(uint4*)&As[buf][kA + 16][mA0]     = ra4[2];
        *(uint4*)&As[buf][kA + 16][mA0 + 4] = ra4[3];
        #pragma unroll
        for (int i = 0; i < 32; i++) Bs[buf][i][tid] = rb[i];
    };

    loadAB(0);
    writeS(0);
    __syncthreads();

    int buf = 0;
    for (int k0 = 0; k0 < KC; k0 += 32) {
        bool nxt = (k0 + 32) < KC;
        if (nxt) loadAB(k0 + 32);

        #pragma unroll
        for (int ks = 0; ks < 4; ks++) {
            int kb = ks * 8;
            uint32_t af[2][4], bf[8][2];
            #pragma unroll
            for (int mt = 0; mt < 2; mt++) {
                int mb = m0w + mt * 16 + g;
                af[mt][0] = As[buf][kb + t][mb];
                af[mt][1] = As[buf][kb + t][mb + 8];
                af[mt][2] = As[buf][kb + t + 4][mb];
                af[mt][3] = As[buf][kb + t + 4][mb + 8];
            }
            #pragma unroll
            for (int nt = 0; nt < 8; nt++) {
                int nb = n0w + nt * 8 + g;
                bf[nt][0] = Bs[buf][kb + t][nb];
                bf[nt][1] = Bs[buf][kb + t + 4][nb];
            }
            #pragma unroll
            for (int mt = 0; mt < 2; mt++)
                #pragma unroll
                for (int nt = 0; nt < 8; nt++)
                    mma_tf32(acc[mt][nt][0], acc[mt][nt][1], acc[mt][nt][2], acc[mt][nt][3],
                             af[mt][0], af[mt][1], af[mt][2], af[mt][3],
                             bf[nt][0], bf[nt][1]);
        }

        if (nxt) {
            writeS(buf ^ 1);
            __syncthreads();
            buf ^= 1;
        }
    }

    #pragma unroll
    for (int mt = 0; mt < 2; mt++) {
        int gm = m0 + m0w + mt * 16 + g;
        #pragma unroll
        for (int nt = 0; nt < 8; nt++) {
            int gn = n0 + n0w + nt * 8 + 2 * t;
            if (gn < Nn)     Cp[(size_t)gm * ldc + gn]           = f2tf32(acc[mt][nt][0]);
            if (gn + 1 < Nn) Cp[(size_t)gm * ldc + gn + 1]       = f2tf32(acc[mt][nt][1]);
            if (gn < Nn)     Cp[(size_t)(gm + 8) * ldc + gn]     = f2tf32(acc[mt][nt][2]);
            if (gn + 1 < Nn) Cp[(size_t)(gm + 8) * ldc + gn + 1] = f2tf32(acc[mt][nt][3]);
        }
    }
}

// ============================================================
// gemm64t: tf32 MMA 64x64 GEMM (proven; x-proj + PV).
// ============================================================
template<int BMODE, int EPI, bool BRAW, bool OU32>
__global__ void __launch_bounds__(128) gemm64t_k(
    const uint32_t* __restrict__ A, size_t sA, int lda,
    const void* __restrict__ Bv, size_t sB, int ldb,
    void* __restrict__ Cv, size_t sC, int ldc,
    int N, int K,
    const float* __restrict__ aux, size_t sAux)
{
    __shared__ uint32_t As[2][16][72];
    __shared__ uint32_t Bs[2][16][72];
    A += (size_t)blockIdx.z * sA;
    const uint32_t* B32 = (const uint32_t*)Bv + (BRAW ? (size_t)blockIdx.z * sB : 0);
    const float*    Bf  = (const float*)Bv    + (BRAW ? 0 : (size_t)blockIdx.z * sB);
    uint32_t* C32 = (uint32_t*)Cv + (size_t)blockIdx.z * sC;
    float*    Cf  = (float*)Cv    + (size_t)blockIdx.z * sC;
    const float* auxp = aux + (size_t)blockIdx.z * sAux;

    const int m0 = blockIdx.y * 64, n0 = blockIdx.x * 64;
    const int tid = threadIdx.x;
    const int warp = tid >> 5, lane = tid & 31;
    const int g = lane >> 2, t = lane & 3;
    const int wm = warp & 1, wn = warp >> 1;
    const int m0w = wm * 32, n0w = wn * 32;

    const int ka = tid & 15;
    const int ma = tid >> 4;
    const int nb64 = tid & 63;
    const int kb2 = tid >> 6;
    const int kb16 = tid & 15;

    float acc[2][4][4];
    #pragma unroll
    for (int i = 0; i < 2; i++)
        #pragma unroll
        for (int j = 0; j < 4; j++)
            #pragma unroll
            for (int r = 0; r < 4; r++) acc[i][j][r] = 0.f;

    uint32_t ra[8], rb[8];

    auto ldB = [&](int gk, int gn) -> uint32_t {
        if (gn >= N || gk >= K) return 0u;
        if (BRAW) return B32[(size_t)(BMODE == 1 ? gn : gk) * ldb + (BMODE == 1 ? gk : gn)];
        else      return f2tf32(Bf[(size_t)(BMODE == 1 ? gn : gk) * ldb + (BMODE == 1 ? gk : gn)]);
    };

    auto loadAB = [&](int k0) {
        #pragma unroll
        for (int i = 0; i < 8; i++) {
            int gk = k0 + ka;
            int m = m0 + ma + 8 * i;
            ra[i] = (gk < K) ? A[(size_t)m * lda + gk] : 0u;
        }
        if (BMODE == 0) {
            #pragma unroll
            for (int i = 0; i < 8; i++)
                rb[i] = ldB(k0 + kb2 + 2 * i, n0 + nb64);
        } else {
            #pragma unroll
            for (int i = 0; i < 8; i++)
                rb[i] = ldB(k0 + kb16, n0 + (tid >> 4) + 8 * i);
        }
    };

    auto writeS = [&](int buf) {
        #pragma unroll
        for (int i = 0; i < 8; i++) As[buf][ka][ma + 8 * i] = ra[i];
        if (BMODE == 1) {
            #pragma unroll
            for (int i = 0; i < 8; i++) Bs[buf][kb16][(tid >> 4) + 8 * i] = rb[i];
        } else {
            #pragma unroll
            for (int i = 0; i < 8; i++) Bs[buf][kb2 + 2 * i][nb64] = rb[i];
        }
    };

    loadAB(0);
    writeS(0);
    __syncthreads();

    int buf = 0;
    for (int k0 = 0; k0 < K; k0 += 16) {
        bool nxt = (k0 + 16) < K;
        if (nxt) loadAB(k0 + 16);

        #pragma unroll
        for (int ks = 0; ks < 2; ks++) {
            int kb = ks * 8;
            uint32_t af[2][4], bf[4][2];
            #pragma unroll
            for (int mt = 0; mt < 2; mt++) {
                int mb = m0w + mt * 16 + g;
                af[mt][0] = As[buf][kb + t][mb];
                af[mt][1] = As[buf][kb + t][mb + 8];
                af[mt][2] = As[buf][kb + t + 4][mb];
                af[mt][3] = As[buf][kb + t + 4][mb + 8];
            }
            #pragma unroll
            for (int nt = 0; nt < 4; nt++) {
                int nb = n0w + nt * 8 + g;
                bf[nt][0] = Bs[buf][kb + t][nb];
                bf[nt][1] = Bs[buf][kb + t + 4][nb];
            }
            #pragma unroll
            for (int mt = 0; mt < 2; mt++)
                #pragma unroll
                for (int nt = 0; nt < 4; nt++)
                    mma_tf32(acc[mt][nt][0], acc[mt][nt][1], acc[mt][nt][2], acc[mt][nt][3],
                             af[mt][0], af[mt][1], af[mt][2], af[mt][3],
                             bf[nt][0], bf[nt][1]);
        }

        if (nxt) {
            writeS(buf ^ 1);
            __syncthreads();
            buf ^= 1;
        }
    }

    #pragma unroll
    for (int mt = 0; mt < 2; mt++) {
        int gm = m0 + m0w + mt * 16 + g;
        float bv0 = (EPI == 1 || EPI == 2) ? auxp[gm] : 0.f;
        float bv8 = (EPI == 1 || EPI == 2) ? auxp[gm + 8] : 0.f;
        #pragma unroll
        for (int nt = 0; nt < 4; nt++) {
            int gn = n0 + n0w + nt * 8 + 2 * t;
            float v0 = acc[mt][nt][0], v1 = acc[mt][nt][1];
            float v2 = acc[mt][nt][2], v3 = acc[mt][nt][3];
            if (EPI == 1) { v0 += bv0; v1 += bv0; v2 += bv8; v3 += bv8; }
            if (EPI == 2) {
                v0 = tanhf(v0 + bv0); v1 = tanhf(v1 + bv0);
                v2 = tanhf(v2 + bv8); v3 = tanhf(v3 + bv8);
            }
            if (EPI == 3) {
                float i0 = (gn < N)     ? 1.f / auxp[gn]     : 0.f;
                float i1 = (gn + 1 < N) ? 1.f / auxp[gn + 1] : 0.f;
                v0 *= i0; v1 *= i1; v2 *= i0; v3 *= i1;
            }
            if (OU32) {
                if (gn < N)     C32[(size_t)gm * ldc + gn]           = f2tf32(v0);
                if (gn + 1 < N) C32[(size_t)gm * ldc + gn + 1]       = f2tf32(v1);
                if (gn < N)     C32[(size_t)(gm + 8) * ldc + gn]     = f2tf32(v2);
                if (gn + 1 < N) C32[(size_t)(gm + 8) * ldc + gn + 1] = f2tf32(v3);
            } else {
                if (gn < N)     Cf[(size_t)gm * ldc + gn]           = v0;
                if (gn + 1 < N) Cf[(size_t)gm * ldc + gn + 1]       = v1;
                if (gn < N)     Cf[(size_t)(gm + 8) * ldc + gn]     = v2;
                if (gn + 1 < N) Cf[(size_t)(gm + 8) * ldc + gn + 1] = v3;
            }
        }
    }
}

// ============================================================
// hout_k: fused proj_h + out. CTA = 128(m) x 64(n) tile, 256 threads.
// Phase 1: h = tanh(Wh[:, :2C] @ xa + beff) -> SMEM hs[128][72] (tf32).
// Phase 2: out = Wo @ h + bo, B fragments straight from hs.
// ============================================================
__global__ void __launch_bounds__(256) hout_k(
    const uint32_t* __restrict__ xa,   // [2C][P] per batch (tf32 bits)
    float* __restrict__ outp)          // [C][P] per batch fp32
{
    __shared__ uint32_t As[2][16][136];
    __shared__ uint32_t Bs[2][16][72];
    __shared__ uint32_t hs[128][72];

    const uint32_t* B = xa + (size_t)blockIdx.z * 2 * C * P;
    float* Co = outp + (size_t)blockIdx.z * C * P;
    const int n0 = blockIdx.x * 64;

    const int tid = threadIdx.x;
    const int warp = tid >> 5, lane = tid & 31;
    const int g = lane >> 2, t = lane & 3;
    const int wm = warp & 3, wn = warp >> 2;     // 4 m-subtiles x 2 n-subtiles
    const int m0w = wm * 32, n0w = wn * 32;

    // A loader: ka = tid&15 (k), maa = tid>>4 (0..15), m = maa + 16*i (i<8)
    const int ka = tid & 15;
    const int maa = tid >> 4;
    // B loader: n = tid&63, k = (tid>>6) + 4*i (i<4)
    const int nb64 = tid & 63;
    const int kb4 = tid >> 6;

    float acc[2][4][4];
    #pragma unroll
    for (int i = 0; i < 2; i++)
        #pragma unroll
        for (int j = 0; j < 4; j++)
            #pragma unroll
            for (int r = 0; r < 4; r++) acc[i][j][r] = 0.f;

    uint32_t ra[8], rb[4];

    // ---------------- phase 1: proj_h ----------------
    auto loadAB1 = [&](int k0) {
        #pragma unroll
        for (int i = 0; i < 8; i++) {
            int m = maa + 16 * i;
            ra[i] = g_wh[(size_t)m * (3*C) + k0 + ka];
        }
        int gn = n0 + nb64;
        bool gok = (gn < P);
        #pragma unroll
        for (int i = 0; i < 4; i++) {
            int gk = k0 + kb4 + 4 * i;
            rb[i] = gok ? B[(size_t)gk * P + gn] : 0u;
        }
    };
    auto writeS1 = [&](int buf) {
        #pragma unroll
        for (int i = 0; i < 8; i++) As[buf][ka][maa + 16 * i] = ra[i];
        #pragma unroll
        for (int i = 0; i < 4; i++) Bs[buf][kb4 + 4 * i][nb64] = rb[i];
    };

    loadAB1(0);
    writeS1(0);
    __syncthreads();

    int buf = 0;
    for (int k0 = 0; k0 < 2*C; k0 += 16) {
        bool nxt = (k0 + 16) < 2*C;
        if (nxt) loadAB1(k0 + 16);

        #pragma unroll
        for (int ks = 0; ks < 2; ks++) {
            int kb = ks * 8;
            uint32_t af[2][4], bf[4][2];
            #pragma unroll
            for (int mt = 0; mt < 2; mt++) {
                int mb = m0w + mt * 16 + g;
                af[mt][0] = As[buf][kb + t][mb];
                af[mt][1] = As[buf][kb + t][mb + 8];
                af[mt][2] = As[buf][kb + t + 4][mb];
                af[mt][3] = As[buf][kb + t + 4][mb + 8];
            }
            #pragma unroll
            for (int nt = 0; nt < 4; nt++) {
                int nb = n0w + nt * 8 + g;
                bf[nt][0] = Bs[buf][kb + t][nb];
                bf[nt][1] = Bs[buf][kb + t + 4][nb];
            }
            #pragma unroll
            for (int mt = 0; mt < 2; mt++)
                #pragma unroll
                for (int nt = 0; nt < 4; nt++)
                    mma_tf32(acc[mt][nt][0], acc[mt][nt][1], acc[mt][nt][2], acc[mt][nt][3],
                             af[mt][0], af[mt][1], af[mt][2], af[mt][3],
                             bf[nt][0], bf[nt][1]);
        }

        if (nxt) {
            writeS1(buf ^ 1);
            __syncthreads();
            buf ^= 1;
        }
    }

    // epilogue phase 1: tanh + beff -> hs (local columns)
    #pragma unroll
    for (int mt = 0; mt < 2; mt++) {
        int gm = m0w + mt * 16 + g;          // 0..127
        float bv0 = g_beff[gm], bv8 = g_beff[gm + 8];
        #pragma unroll
        for (int nt = 0; nt < 4; nt++) {
            int nl = n0w + nt * 8 + 2 * t;   // local col 0..63
            hs[gm][nl]         = f2tf32(tanhf(acc[mt][nt][0] + bv0));
            hs[gm][nl + 1]     = f2tf32(tanhf(acc[mt][nt][1] + bv0));
            hs[gm + 8][nl]     = f2tf32(tanhf(acc[mt][nt][2] + bv8));
            hs[gm + 8][nl + 1] = f2tf32(tanhf(acc[mt][nt][3] + bv8));
        }
    }
    __syncthreads();

    // ---------------- phase 2: out = Wo @ h ----------------
    #pragma unroll
    for (int i = 0; i < 2; i++)
        #pragma unroll
        for (int j = 0; j < 4; j++)
            #pragma unroll
            for (int r = 0; r < 4; r++) acc[i][j][r] = 0.f;

    auto loadA2 = [&](int k0) {
        #pragma unroll
        for (int i = 0; i < 8; i++) {
            int m = maa + 16 * i;
            ra[i] = g_wo[(size_t)m * C + k0 + ka];
        }
    };
    auto writeS2 = [&](int buf2) {
        #pragma unroll
        for (int i = 0; i < 8; i++) As[buf2][ka][maa + 16 * i] = ra[i];
    };

    loadA2(0);
    writeS2(0);
    __syncthreads();

    buf = 0;
    for (int k0 = 0; k0 < C; k0 += 16) {
        bool nxt = (k0 + 16) < C;
        if (nxt) loadA2(k0 + 16);

        #pragma unroll
        for (int ks = 0; ks < 2; ks++) {
            int kb = ks * 8;
            uint32_t af[2][4], bf[4][2];
            #pragma unroll
            for (int mt = 0; mt < 2; mt++) {
                int mb = m0w + mt * 16 + g;
                af[mt][0] = As[buf][kb + t][mb];
                af[mt][1] = As[buf][kb + t][mb + 8];
                af[mt][2] = As[buf][kb + t + 4][mb];
                af[mt][3] = As[buf][kb + t + 4][mb + 8];
            }
            #pragma unroll
            for (int nt = 0; nt < 4; nt++) {
                int nb = n0w + nt * 8 + g;
                bf[nt][0] = hs[k0 + kb + t][nb];
                bf[nt][1] = hs[k0 + kb + t + 4][nb];
            }
            #pragma unroll
            for (int mt = 0; mt < 2; mt++)
                #pragma unroll
                for (int nt = 0; nt < 4; nt++)
                    mma_tf32(acc[mt][nt][0], acc[mt][nt][1], acc[mt][nt][2], acc[mt][nt][3],
                             af[mt][0], af[mt][1], af[mt][2], af[mt][3],
                             bf[nt][0], bf[nt][1]);
        }

        if (nxt) {
            writeS2(buf ^ 1);
            __syncthreads();
            buf ^= 1;
        }
    }

    // epilogue phase 2: + b_o (stashed in hs row? no: use g_beff? separate) -> fp32
    #pragma unroll
    for (int mt = 0; mt < 2; mt++) {
        int gm = m0w + mt * 16 + g;
        #pragma unroll
        for (int nt = 0; nt < 4; nt++) {
            int gn = n0 + n0w + nt * 8 + 2 * t;
            if (gn < P) {
                Co[(size_t)gm * P + gn]       = acc[mt][nt][0];
                Co[(size_t)(gm + 8) * P + gn] = acc[mt][nt][2];
            }
            if (gn + 1 < P) {
                Co[(size_t)gm * P + gn + 1]       = acc[mt][nt][1];
                Co[(size_t)(gm + 8) * P + gn + 1] = acc[mt][nt][3];
            }
        }
    }
}

// small epilogue: add b_o to out (kept separate to avoid passing bias through hout)
__global__ void addbias_k(float* __restrict__ outp, const float* __restrict__ bo)
{
    size_t i = (size_t)blockIdx.x * 256 + threadIdx.x;
    if (i < (size_t)NB * C * P) {
        int m = (i / P) % C;
        outp[i] += bo[m];
    }
}

// ============================================================
// gemm_big: exp-scores + row sums. tf32 MMA, BK=16.
// ============================================================
__global__ void __launch_bounds__(256) gemm_big_k(
    const uint32_t* __restrict__ Aq,
    const uint32_t* __restrict__ Bk,
    uint32_t* __restrict__ Cs,
    float* __restrict__ rs)
{
    __shared__ uint32_t As[2][16][136];
    __shared__ uint32_t Bs[2][16][136];
    const uint32_t* Ab = Aq + (size_t)blockIdx.z * C * P;
    const uint32_t* Bb = Bk + (size_t)blockIdx.z * C * D;
    uint32_t* Cb = Cs + (size_t)blockIdx.z * (size_t)P * D;
    float* rsb = rs + (size_t)blockIdx.z * P;

    const int m0 = blockIdx.y * 128, n0 = blockIdx.x * 128;
    const int tid = threadIdx.x;
    const int kf = tid >> 5, e4 = (tid & 31) * 4;
    const int warp = tid >> 5, lane = tid & 31;
    const int g = lane >> 2, t = lane & 3;
    const int wm = warp & 3, wn = warp >> 2;
    const int m0w = wm * 32, n0w = wn * 64;

    float acc[2][8][4];
    #pragma unroll
    for (int i = 0; i < 2; i++)
        #pragma unroll
        for (int j = 0; j < 8; j++)
            #pragma unroll
            for (int r = 0; r < 4; r++) acc[i][j][r] = 0.f;

    uint4 ra0, ra1, rb0, rb1;
    auto ld4A = [&](int krow, uint4& r) {
        const uint32_t* src = Ab + (size_t)krow * P;
        int m = m0 + e4;
        if (m + 3 < P) r = *(const uint4*)(src + m);
        else {
            r.x = (m+0 < P) ? src[m+0] : 0u;
            r.y = (m+1 < P) ? src[m+1] : 0u;
            r.z = (m+2 < P) ? src[m+2] : 0u;
            r.w = (m+3 < P) ? src[m+3] : 0u;
        }
    };
    auto ld4B = [&](int krow, uint4& r) {
        const uint32_t* src = Bb + (size_t)krow * D;
        int n = n0 + e4;
        if (n + 3 < D) r = *(const uint4*)(src + n);
        else {
            r.x = (n+0 < D) ? src[n+0] : 0u;
            r.y = (n+1 < D) ? src[n+1] : 0u;
            r.z = (n+2 < D) ? src[n+2] : 0u;
            r.w = (n+3 < D) ? src[n+3] : 0u;
        }
    };
    auto loadReg = [&](int k0) {
        ld4A(k0 + kf, ra0);
        ld4A(k0 + kf + 8, ra1);
        ld4B(k0 + kf, rb0);
        ld4B(k0 + kf + 8, rb1);
    };
    auto writeS = [&](int buf) {
        *(uint4*)&As[buf][kf][e4]   = ra0;
        *(uint4*)&As[buf][kf+8][e4] = ra1;
        *(uint4*)&Bs[buf][kf][e4]   = rb0;
        *(uint4*)&Bs[buf][kf+8][e4] = rb1;
    };

    loadReg(0);
    writeS(0);
    __syncthreads();

    int buf = 0;
    for (int k0 = 0; k0 < C; k0 += 16) {
        bool nxt = (k0 + 16) < C;
        if (nxt) loadReg(k0 + 16);

        #pragma unroll
        for (int ks = 0; ks < 2; ks++) {
            int kb = ks * 8;
            uint32_t af[2][4], bf[8][2];
            #pragma unroll
            for (int mt = 0; mt < 2; mt++) {
                int mb = m0w + mt * 16 + g;
                af[mt][0] = As[buf][kb + t][mb];
                af[mt][1] = As[buf][kb + t][mb + 8];
                af[mt][2] = As[buf][kb + t + 4][mb];
                af[mt][3] = As[buf][kb + t + 4][mb + 8];
            }
            #pragma unroll
            for (int nt = 0; nt < 8; nt++) {
                int nb = n0w + nt * 8 + g;
                bf[nt][0] = Bs[buf][kb + t][nb];
                bf[nt][1] = Bs[buf][kb + t + 4][nb];
            }
            #pragma unroll
            for (int mt = 0; mt < 2; mt++)
                #pragma unroll
                for (int nt = 0; nt < 8; nt++)
                    mma_tf32(acc[mt][nt][0], acc[mt][nt][1], acc[mt][nt][2], acc[mt][nt][3],
                             af[mt][0], af[mt][1], af[mt][2], af[mt][3],
                             bf[nt][0], bf[nt][1]);
        }

        if (nxt) {
            writeS(buf ^ 1);
            __syncthreads();
            buf ^= 1;
        }
    }

    #pragma unroll
    for (int mt = 0; mt < 2; mt++) {
        int gm = m0 + m0w + mt * 16 + g;
        float s0 = 0.f, s1 = 0.f;
        #pragma unroll
        for (int nt = 0; nt < 8; nt++) {
            int gn = n0 + n0w + nt * 8 + 2 * t;
            bool c0 = (gn < D), c1 = (gn + 1 < D);
            float e0 = __expf(acc[mt][nt][0]);
            float e1 = __expf(acc[mt][nt][1]);
            float e2 = __expf(acc[mt][nt][2]);
            float e3 = __expf(acc[mt][nt][3]);
            if (gm < P) {
                if (c0) Cb[(size_t)gm * D + gn]     = f2tf32(e0);
                if (c1) Cb[(size_t)gm * D + gn + 1] = f2tf32(e1);
            }
            if (gm + 8 < P) {
                if (c0) Cb[(size_t)(gm + 8) * D + gn]     = f2tf32(e2);
                if (c1) Cb[(size_t)(gm + 8) * D + gn + 1] = f2tf32(e3);
            }
            s0 += (c0 ? e0 : 0.f) + (c1 ? e1 : 0.f);
            s1 += (c0 ? e2 : 0.f) + (c1 ? e3 : 0.f);
        }
        s0 += __shfl_xor_sync(0xffffffff, s0, 1);
        s0 += __shfl_xor_sync(0xffffffff, s0, 2);
        s1 += __shfl_xor_sync(0xffffffff, s1, 1);
        s1 += __shfl_xor_sync(0xffffffff, s1, 2);
        if (t == 0) {
            if (gm < P)     atomicAdd(&rsb[gm], s0);
            if (gm + 8 < P) atomicAdd(&rsb[gm + 8], s1);
        }
    }
}

// -------- beff = b_h + W_h[:,2C:3C] @ v_c; v_c from constant c0 --------
__global__ void beff_k(const float* __restrict__ w_vc, const float* __restrict__ c0,
                       const float* __restrict__ w_h, const float* __restrict__ b_h,
                       float* __restrict__ beff)
{
    __shared__ float vc[C];
    int c = threadIdx.x;
    float s = 0.f;
    for (int ci = 0; ci < C; ci++) {
        float ws = 0.f;
        #pragma unroll
        for (int t = 0; t < 9; t++) ws += w_vc[((size_t)c * C + ci) * 9 + t];
        s += ws * c0[ci];
    }
    vc[c] = s;
    __syncthreads();
    float r = b_h[c];
    for (int j = 0; j < C; j++) r += w_h[(size_t)c * (3*C) + 2*C + j] * vc[j];
    beff[c] = r;
}

extern "C" void kernel_launch(void* const* d_in, const int* in_sizes, int n_in,
                              void* d_out, int out_size)
{
    const float* inp  = (const float*)d_in[0];
    const float* c0   = (const float*)d_in[1];
    const float* w_x  = (const float*)d_in[2];
    const float* b_x  = (const float*)d_in[3];
    const float* w_qx = (const float*)d_in[4];
    const float* w_kx = (const float*)d_in[6];
    const float* w_vx = (const float*)d_in[8];
    const float* w_vc = (const float*)d_in[9];
    const float* w_h  = (const float*)d_in[14];
    const float* b_h  = (const float*)d_in[15];
    const float* w_o  = (const float*)d_in[16];
    const float* b_o  = (const float*)d_in[17];
    float* out = (float*)d_out;

    uint32_t *xa, *q, *k, *v, *sc;
    float *rs, *beff;
    cudaGetSymbolAddress((void**)&xa,   g_xa);
    cudaGetSymbolAddress((void**)&q,    g_q);
    cudaGetSymbolAddress((void**)&k,    g_k);
    cudaGetSymbolAddress((void**)&v,    g_v);
    cudaGetSymbolAddress((void**)&sc,   g_sc);
    cudaGetSymbolAddress((void**)&rs,   g_rs);
    cudaGetSymbolAddress((void**)&beff, g_beff);
    uint32_t *wx;
    cudaGetSymbolAddress((void**)&wx, g_wx);

    const int NT_P = (P + 63) / 64;      // 21

    // constants and merged weight pre-conversion
    beff_k<<<1, C>>>(w_vc, c0, w_h, b_h, beff);
    preconv_all_k<<<(KC*C + 255)/256, 256>>>(w_x, w_h, w_o, w_qx, w_kx, w_vx);

    // x = W_x @ inp + b_x -> g_xa rows [0,128) as tf32 bits
    gemm64t_k<0,1,false,true><<<dim3(NT_P, 2, NB), 128>>>(
        wx, 0, C, inp, (size_t)C*P, P, xa, (size_t)2*C*P, P, P, C, b_x, 0);

    // q/k/v 3x3 convs, tf32 MMA mega-launch
    qkv_mega_k<<<dim3(62, 1, NB), 128>>>(xa, q, k, v);

    // ex[p,d] = exp(q^T k) + row sums (fused)
    gemm_big_k<<<dim3((D + 127)/128, (P + 127)/128, NB), 256>>>(q, k, sc, rs);

    // a0[c,p] = (v @ ex^T)[c,p] / rs[p]
    gemm64t_k<1,3,true,true><<<dim3(NT_P, 2, NB), 128>>>(
        v, (size_t)C*D, D, sc, (size_t)P*D, D, xa + (size_t)C*P, (size_t)2*C*P, P,
        P, D, rs, P);

    // out = Wo @ tanh(Wh @ [x;a0] + beff)   (fused, b_o added after)
    hout_k<<<dim3(NT_P, 1, NB), 256>>>(xa, out);
    addbias_k<<<((size_t)NB*C*P + 255)/256, 256>>>(out, b_o);
}

// round 17
// speedup vs baseline: 1.2036x; 1.0227x over previous
#include <cuda_runtime.h>
#include <cstdint>
#include <cstddef>

// Problem dims
#define NB 8
#define C 128
#define HH 36
#define WW 36
#define P (HH*WW)          // 1296 query tokens
#define HV 34
#define WV 34
#define D (HV*WV)          // 1156 key/value tokens
#define KC (C*9)           // 1152 im2col K

// -------- scratch (static device memory; no allocation APIs) --------
__device__ uint32_t g_xa[(size_t)NB*2*C*P];   // rows 0..127: x, rows 128..255: a0
__device__ uint32_t g_q[(size_t)NB*C*P];
__device__ uint32_t g_k[(size_t)NB*C*D];
__device__ uint32_t g_v[(size_t)NB*C*D];
__device__ uint32_t g_sc[(size_t)NB*(size_t)P*D]; // exp(scores) tf32 bits
__device__ float    g_rs[(size_t)NB*P];           // row sums of exp
__device__ float    g_beff[C];
__device__ uint32_t g_wx[C*C];
__device__ uint32_t g_wh[C*3*C];
__device__ uint32_t g_wo[C*C];
// qkv weights pre-transposed to [kg][m], kg = t*128 + ci (t-major K order)
__device__ uint32_t g_wqt[KC*C];
__device__ uint32_t g_wkt[KC*C];
__device__ uint32_t g_wvt[KC*C];

// -------- tf32 helpers --------
__device__ __forceinline__ uint32_t f2tf32(float f) {
    uint32_t u;
    asm("cvt.rna.tf32.f32 %0, %1;" : "=r"(u) : "f"(f));
    return u;
}

__device__ __forceinline__ void mma_tf32(
    float& c0, float& c1, float& c2, float& c3,
    uint32_t a0, uint32_t a1, uint32_t a2, uint32_t a3,
    uint32_t b0, uint32_t b1)
{
    asm volatile(
        "mma.sync.aligned.m16n8k8.row.col.f32.tf32.tf32.f32 "
        "{%0,%1,%2,%3}, {%4,%5,%6,%7}, {%8,%9}, {%0,%1,%2,%3};"
        : "+f"(c0), "+f"(c1), "+f"(c2), "+f"(c3)
        : "r"(a0), "r"(a1), "r"(a2), "r"(a3), "r"(b0), "r"(b1));
}

// -------- cp.async helpers --------
__device__ __forceinline__ uint32_t sptr(const void* p) {
    return (uint32_t)__cvta_generic_to_shared(p);
}
__device__ __forceinline__ void cpa4(uint32_t dst, const void* src, bool pred) {
    int sz = pred ? 4 : 0;
    asm volatile("cp.async.ca.shared.global [%0], [%1], 4, %2;\n"
                 :: "r"(dst), "l"(src), "r"(sz));
}
__device__ __forceinline__ void cpa16(uint32_t dst, const void* src) {
    asm volatile("cp.async.cg.shared.global [%0], [%1], 16;\n"
                 :: "r"(dst), "l"(src));
}
__device__ __forceinline__ void cpa_commit() {
    asm volatile("cp.async.commit_group;\n" ::: "memory");
}
__device__ __forceinline__ void cpa_wait0() {
    asm volatile("cp.async.wait_group 0;\n" ::: "memory");
}

// -------- merged weight pre-conversion (one launch) --------
__global__ void preconv_all_k(const float* __restrict__ wx, const float* __restrict__ wh,
                              const float* __restrict__ wo,
                              const float* __restrict__ wq, const float* __restrict__ wk,
                              const float* __restrict__ wv)
{
    int i = blockIdx.x * 256 + threadIdx.x;
    if (i < NB * P) g_rs[i] = 0.f;
    if (i < C*C)   { g_wx[i] = f2tf32(wx[i]); g_wo[i] = f2tf32(wo[i]); }
    if (i < C*3*C) g_wh[i] = f2tf32(wh[i]);
    if (i < KC * C) {
        int kg = i / C, m = i % C;
        int t = kg >> 7, ci = kg & 127;
        size_t src = ((size_t)m * C + ci) * 9 + t;
        g_wqt[i] = f2tf32(wq[src]);
        g_wkt[i] = f2tf32(wk[src]);
        g_wvt[i] = f2tf32(wv[src]);
    }
}

// ============================================================
// qkv_mega: all three 3x3 conv GEMMs in ONE launch, tf32 MMA core.
// CTA tile 64(m) x 128(n), 128 threads, BK = 32.
// Loaders converted to cp.async (register-free, latency-hidden).
// ============================================================
__global__ void __launch_bounds__(128, 4) qkv_mega_k(
    const uint32_t* __restrict__ xa,
    uint32_t* __restrict__ qo, uint32_t* __restrict__ ko, uint32_t* __restrict__ vo)
{
    __shared__ uint32_t As[2][32][72];
    __shared__ uint32_t Bs[2][32][136];

    const int bz = blockIdx.z;
    const int tile = blockIdx.x;
    bool qmode; int my, nx;
    if (tile < 22) { qmode = true;  my = tile / 11; nx = tile % 11; }
    else { int t2 = tile - 22; qmode = false; my = t2 / 10; nx = t2 % 10; }

    const uint32_t* At = qmode ? g_wqt : ((my < 2) ? g_wkt : g_wvt);
    const int m0 = qmode ? my * 64 : (my & 1) * 64;
    const int Nn = qmode ? P : D;
    uint32_t* Cp = qmode ? (qo + (size_t)bz * C * P)
                         : ((my < 2) ? ko : vo) + (size_t)bz * C * D;
    const uint32_t* B = xa + (size_t)bz * 2 * C * P;
    const int n0 = nx * 128;
    const int ldc = Nn;

    const int tid = threadIdx.x;
    const int warp = tid >> 5, lane = tid & 31;
    const int g = lane >> 2, t = lane & 3;
    const int wm = warp & 1, wn = warp >> 1;
    const int m0w = wm * 32, n0w = wn * 64;

    // A loader slots: rows kA, kA+16; 8 consecutive m per thread (2x cp.async16)
    const int kA = tid >> 3;
    const int mA0 = (tid & 7) * 8;

    int p = n0 + tid;
    bool npred; int iy, ix;
    if (qmode) { npred = (p < P); if (p >= P) p = 0; iy = p / WW; ix = p % WW; }
    else       { npred = (p < D); if (p >= D) p = 0; iy = p / WV; ix = p % WV; }

    float acc[2][8][4];
    #pragma unroll
    for (int i = 0; i < 2; i++)
        #pragma unroll
        for (int j = 0; j < 8; j++)
            #pragma unroll
            for (int r = 0; r < 4; r++) acc[i][j][r] = 0.f;

    auto issueAB = [&](int k0, int buf) {
        // A: 2 rows x 2 x 16B
        #pragma unroll
        for (int h = 0; h < 2; h++) {
            const uint32_t* src = At + (size_t)(k0 + kA + 16 * h) * C + m0 + mA0;
            cpa16(sptr(&As[buf][kA + 16 * h][mA0]),     src);
            cpa16(sptr(&As[buf][kA + 16 * h][mA0 + 4]), src + 4);
        }
        // B: 32 scalar gathers from x (zero-fill on pad)
        int tt = k0 >> 7;                 // constant within 32-chunk
        int ky = tt / 3, kx = tt - ky * 3;
        int cb = k0 & 127;
        if (qmode) {
            int sy = iy + ky - 1, sx = ix + kx - 1;
            bool pr = npred && sy >= 0 && sy < HH && sx >= 0 && sx < WW;
            int rowb = pr ? (sy * WW + sx) : 0;
            const uint32_t* src = B + (size_t)cb * P + rowb;
            #pragma unroll
            for (int i = 0; i < 32; i++)
                cpa4(sptr(&Bs[buf][i][tid]), src + (size_t)i * P, pr);
        } else {
            int rowb = (iy + ky) * WW + (ix + kx);
            const uint32_t* src = B + (size_t)cb * P + rowb;
            #pragma unroll
            for (int i = 0; i < 32; i++)
                cpa4(sptr(&Bs[buf][i][tid]), src + (size_t)i * P, npred);
        }
        cpa_commit();
    };

    issueAB(0, 0);
    cpa_wait0();
    __syncthreads();

    int buf = 0;
    for (int k0 = 0; k0 < KC; k0 += 32) {
        bool nxt = (k0 + 32) < KC;
        if (nxt) issueAB(k0 + 32, buf ^ 1);

        #pragma unroll
        for (int ks = 0; ks < 4; ks++) {
            int kb = ks * 8;
            uint32_t af[2][4], bf[8][2];
            #pragma unroll
            for (int mt = 0; mt < 2; mt++) {
                int mb = m0w + mt * 16 + g;
                af[mt][0] = As[buf][kb + t][mb];
                af[mt][1] = As[buf][kb + t][mb + 8];
                af[mt][2] = As[buf][kb + t + 4][mb];
                af[mt][3] = As[buf][kb + t + 4][mb + 8];
            }
            #pragma unroll
            for (int nt = 0; nt < 8; nt++) {
                int nb = n0w + nt * 8 + g;
                bf[nt][0] = Bs[buf][kb + t][nb];
                bf[nt][1] = Bs[buf][kb + t + 4][nb];
            }
            #pragma unroll
            for (int mt = 0; mt < 2; mt++)
                #pragma unroll
                for (int nt = 0; nt < 8; nt++)
                    mma_tf32(acc[mt][nt][0], acc[mt][nt][1], acc[mt][nt][2], acc[mt][nt][3],
                             af[mt][0], af[mt][1], af[mt][2], af[mt][3],
                             bf[nt][0], bf[nt][1]);
        }

        if (nxt) {
            cpa_wait0();
            __syncthreads();
            buf ^= 1;
        }
    }

    #pragma unroll
    for (int mt = 0; mt < 2; mt++) {
        int gm = m0 + m0w + mt * 16 + g;
        #pragma unroll
        for (int nt = 0; nt < 8; nt++) {
            int gn = n0 + n0w + nt * 8 + 2 * t;
            if (gn < Nn)     Cp[(size_t)gm * ldc + gn]           = f2tf32(acc[mt][nt][0]);
            if (gn + 1 < Nn) Cp[(size_t)gm * ldc + gn + 1]       = f2tf32(acc[mt][nt][1]);
            if (gn < Nn)     Cp[(size_t)(gm + 8) * ldc + gn]     = f2tf32(acc[mt][nt][2]);
            if (gn + 1 < Nn) Cp[(size_t)(gm + 8) * ldc + gn + 1] = f2tf32(acc[mt][nt][3]);
        }
    }
}

// ============================================================
// gemm64t: tf32 MMA 64x64 GEMM (proven; x-proj + PV).
// ============================================================
template<int BMODE, int EPI, bool BRAW, bool OU32>
__global__ void __launch_bounds__(128) gemm64t_k(
    const uint32_t* __restrict__ A, size_t sA, int lda,
    const void* __restrict__ Bv, size_t sB, int ldb,
    void* __restrict__ Cv, size_t sC, int ldc,
    int N, int K,
    const float* __restrict__ aux, size_t sAux)
{
    __shared__ uint32_t As[2][16][72];
    __shared__ uint32_t Bs[2][16][72];
    A += (size_t)blockIdx.z * sA;
    const uint32_t* B32 = (const uint32_t*)Bv + (BRAW ? (size_t)blockIdx.z * sB : 0);
    const float*    Bf  = (const float*)Bv    + (BRAW ? 0 : (size_t)blockIdx.z * sB);
    uint32_t* C32 = (uint32_t*)Cv + (size_t)blockIdx.z * sC;
    float*    Cf  = (float*)Cv    + (size_t)blockIdx.z * sC;
    const float* auxp = aux + (size_t)blockIdx.z * sAux;

    const int m0 = blockIdx.y * 64, n0 = blockIdx.x * 64;
    const int tid = threadIdx.x;
    const int warp = tid >> 5, lane = tid & 31;
    const int g = lane >> 2, t = lane & 3;
    const int wm = warp & 1, wn = warp >> 1;
    const int m0w = wm * 32, n0w = wn * 32;

    const int ka = tid & 15;
    const int ma = tid >> 4;
    const int nb64 = tid & 63;
    const int kb2 = tid >> 6;
    const int kb16 = tid & 15;

    float acc[2][4][4];
    #pragma unroll
    for (int i = 0; i < 2; i++)
        #pragma unroll
        for (int j = 0; j < 4; j++)
            #pragma unroll
            for (int r = 0; r < 4; r++) acc[i][j][r] = 0.f;

    uint32_t ra[8], rb[8];

    auto ldB = [&](int gk, int gn) -> uint32_t {
        if (gn >= N || gk >= K) return 0u;
        if (BRAW) return B32[(size_t)(BMODE == 1 ? gn : gk) * ldb + (BMODE == 1 ? gk : gn)];
        else      return f2tf32(Bf[(size_t)(BMODE == 1 ? gn : gk) * ldb + (BMODE == 1 ? gk : gn)]);
    };

    auto loadAB = [&](int k0) {
        #pragma unroll
        for (int i = 0; i < 8; i++) {
            int gk = k0 + ka;
            int m = m0 + ma + 8 * i;
            ra[i] = (gk < K) ? A[(size_t)m * lda + gk] : 0u;
        }
        if (BMODE == 0) {
            #pragma unroll
            for (int i = 0; i < 8; i++)
                rb[i] = ldB(k0 + kb2 + 2 * i, n0 + nb64);
        } else {
            #pragma unroll
            for (int i = 0; i < 8; i++)
                rb[i] = ldB(k0 + kb16, n0 + (tid >> 4) + 8 * i);
        }
    };

    auto writeS = [&](int buf) {
        #pragma unroll
        for (int i = 0; i < 8; i++) As[buf][ka][ma + 8 * i] = ra[i];
        if (BMODE == 1) {
            #pragma unroll
            for (int i = 0; i < 8; i++) Bs[buf][kb16][(tid >> 4) + 8 * i] = rb[i];
        } else {
            #pragma unroll
            for (int i = 0; i < 8; i++) Bs[buf][kb2 + 2 * i][nb64] = rb[i];
        }
    };

    loadAB(0);
    writeS(0);
    __syncthreads();

    int buf = 0;
    for (int k0 = 0; k0 < K; k0 += 16) {
        bool nxt = (k0 + 16) < K;
        if (nxt) loadAB(k0 + 16);

        #pragma unroll
        for (int ks = 0; ks < 2; ks++) {
            int kb = ks * 8;
            uint32_t af[2][4], bf[4][2];
            #pragma unroll
            for (int mt = 0; mt < 2; mt++) {
                int mb = m0w + mt * 16 + g;
                af[mt][0] = As[buf][kb + t][mb];
                af[mt][1] = As[buf][kb + t][mb + 8];
                af[mt][2] = As[buf][kb + t + 4][mb];
                af[mt][3] = As[buf][kb + t + 4][mb + 8];
            }
            #pragma unroll
            for (int nt = 0; nt < 4; nt++) {
                int nb = n0w + nt * 8 + g;
                bf[nt][0] = Bs[buf][kb + t][nb];
                bf[nt][1] = Bs[buf][kb + t + 4][nb];
            }
            #pragma unroll
            for (int mt = 0; mt < 2; mt++)
                #pragma unroll
                for (int nt = 0; nt < 4; nt++)
                    mma_tf32(acc[mt][nt][0], acc[mt][nt][1], acc[mt][nt][2], acc[mt][nt][3],
                             af[mt][0], af[mt][1], af[mt][2], af[mt][3],
                             bf[nt][0], bf[nt][1]);
        }

        if (nxt) {
            writeS(buf ^ 1);
            __syncthreads();
            buf ^= 1;
        }
    }

    #pragma unroll
    for (int mt = 0; mt < 2; mt++) {
        int gm = m0 + m0w + mt * 16 + g;
        float bv0 = (EPI == 1 || EPI == 2) ? auxp[gm] : 0.f;
        float bv8 = (EPI == 1 || EPI == 2) ? auxp[gm + 8] : 0.f;
        #pragma unroll
        for (int nt = 0; nt < 4; nt++) {
            int gn = n0 + n0w + nt * 8 + 2 * t;
            float v0 = acc[mt][nt][0], v1 = acc[mt][nt][1];
            float v2 = acc[mt][nt][2], v3 = acc[mt][nt][3];
            if (EPI == 1) { v0 += bv0; v1 += bv0; v2 += bv8; v3 += bv8; }
            if (EPI == 2) {
                v0 = tanhf(v0 + bv0); v1 = tanhf(v1 + bv0);
                v2 = tanhf(v2 + bv8); v3 = tanhf(v3 + bv8);
            }
            if (EPI == 3) {
                float i0 = (gn < N)     ? 1.f / auxp[gn]     : 0.f;
                float i1 = (gn + 1 < N) ? 1.f / auxp[gn + 1] : 0.f;
                v0 *= i0; v1 *= i1; v2 *= i0; v3 *= i1;
            }
            if (OU32) {
                if (gn < N)     C32[(size_t)gm * ldc + gn]           = f2tf32(v0);
                if (gn + 1 < N) C32[(size_t)gm * ldc + gn + 1]       = f2tf32(v1);
                if (gn < N)     C32[(size_t)(gm + 8) * ldc + gn]     = f2tf32(v2);
                if (gn + 1 < N) C32[(size_t)(gm + 8) * ldc + gn + 1] = f2tf32(v3);
            } else {
                if (gn < N)     Cf[(size_t)gm * ldc + gn]           = v0;
                if (gn + 1 < N) Cf[(size_t)gm * ldc + gn + 1]       = v1;
                if (gn < N)     Cf[(size_t)(gm + 8) * ldc + gn]     = v2;
                if (gn + 1 < N) Cf[(size_t)(gm + 8) * ldc + gn + 1] = v3;
            }
        }
    }
}

// ============================================================
// hout_k: fused proj_h + out. CTA = 128(m) x 64(n) tile, 256 threads.
// ============================================================
__global__ void __launch_bounds__(256) hout_k(
    const uint32_t* __restrict__ xa,
    float* __restrict__ outp)
{
    __shared__ uint32_t As[2][16][136];
    __shared__ uint32_t Bs[2][16][72];
    __shared__ uint32_t hs[128][72];

    const uint32_t* B = xa + (size_t)blockIdx.z * 2 * C * P;
    float* Co = outp + (size_t)blockIdx.z * C * P;
    const int n0 = blockIdx.x * 64;

    const int tid = threadIdx.x;
    const int warp = tid >> 5, lane = tid & 31;
    const int g = lane >> 2, t = lane & 3;
    const int wm = warp & 3, wn = warp >> 2;
    const int m0w = wm * 32, n0w = wn * 32;

    const int ka = tid & 15;
    const int maa = tid >> 4;
    const int nb64 = tid & 63;
    const int kb4 = tid >> 6;

    float acc[2][4][4];
    #pragma unroll
    for (int i = 0; i < 2; i++)
        #pragma unroll
        for (int j = 0; j < 4; j++)
            #pragma unroll
            for (int r = 0; r < 4; r++) acc[i][j][r] = 0.f;

    uint32_t ra[8], rb[4];

    // ---------------- phase 1: proj_h ----------------
    auto loadAB1 = [&](int k0) {
        #pragma unroll
        for (int i = 0; i < 8; i++) {
            int m = maa + 16 * i;
            ra[i] = g_wh[(size_t)m * (3*C) + k0 + ka];
        }
        int gn = n0 + nb64;
        bool gok = (gn < P);
        #pragma unroll
        for (int i = 0; i < 4; i++) {
            int gk = k0 + kb4 + 4 * i;
            rb[i] = gok ? B[(size_t)gk * P + gn] : 0u;
        }
    };
    auto writeS1 = [&](int buf) {
        #pragma unroll
        for (int i = 0; i < 8; i++) As[buf][ka][maa + 16 * i] = ra[i];
        #pragma unroll
        for (int i = 0; i < 4; i++) Bs[buf][kb4 + 4 * i][nb64] = rb[i];
    };

    loadAB1(0);
    writeS1(0);
    __syncthreads();

    int buf = 0;
    for (int k0 = 0; k0 < 2*C; k0 += 16) {
        bool nxt = (k0 + 16) < 2*C;
        if (nxt) loadAB1(k0 + 16);

        #pragma unroll
        for (int ks = 0; ks < 2; ks++) {
            int kb = ks * 8;
            uint32_t af[2][4], bf[4][2];
            #pragma unroll
            for (int mt = 0; mt < 2; mt++) {
                int mb = m0w + mt * 16 + g;
                af[mt][0] = As[buf][kb + t][mb];
                af[mt][1] = As[buf][kb + t][mb + 8];
                af[mt][2] = As[buf][kb + t + 4][mb];
                af[mt][3] = As[buf][kb + t + 4][mb + 8];
            }
            #pragma unroll
            for (int nt = 0; nt < 4; nt++) {
                int nb = n0w + nt * 8 + g;
                bf[nt][0] = Bs[buf][kb + t][nb];
                bf[nt][1] = Bs[buf][kb + t + 4][nb];
            }
            #pragma unroll
            for (int mt = 0; mt < 2; mt++)
                #pragma unroll
                for (int nt = 0; nt < 4; nt++)
                    mma_tf32(acc[mt][nt][0], acc[mt][nt][1], acc[mt][nt][2], acc[mt][nt][3],
                             af[mt][0], af[mt][1], af[mt][2], af[mt][3],
                             bf[nt][0], bf[nt][1]);
        }

        if (nxt) {
            writeS1(buf ^ 1);
            __syncthreads();
            buf ^= 1;
        }
    }

    #pragma unroll
    for (int mt = 0; mt < 2; mt++) {
        int gm = m0w + mt * 16 + g;
        float bv0 = g_beff[gm], bv8 = g_beff[gm + 8];
        #pragma unroll
        for (int nt = 0; nt < 4; nt++) {
            int nl = n0w + nt * 8 + 2 * t;
            hs[gm][nl]         = f2tf32(tanhf(acc[mt][nt][0] + bv0));
            hs[gm][nl + 1]     = f2tf32(tanhf(acc[mt][nt][1] + bv0));
            hs[gm + 8][nl]     = f2tf32(tanhf(acc[mt][nt][2] + bv8));
            hs[gm + 8][nl + 1] = f2tf32(tanhf(acc[mt][nt][3] + bv8));
        }
    }
    __syncthreads();

    // ---------------- phase 2: out = Wo @ h ----------------
    #pragma unroll
    for (int i = 0; i < 2; i++)
        #pragma unroll
        for (int j = 0; j < 4; j++)
            #pragma unroll
            for (int r = 0; r < 4; r++) acc[i][j][r] = 0.f;

    auto loadA2 = [&](int k0) {
        #pragma unroll
        for (int i = 0; i < 8; i++) {
            int m = maa + 16 * i;
            ra[i] = g_wo[(size_t)m * C + k0 + ka];
        }
    };
    auto writeS2 = [&](int buf2) {
        #pragma unroll
        for (int i = 0; i < 8; i++) As[buf2][ka][maa + 16 * i] = ra[i];
    };

    loadA2(0);
    writeS2(0);
    __syncthreads();

    buf = 0;
    for (int k0 = 0; k0 < C; k0 += 16) {
        bool nxt = (k0 + 16) < C;
        if (nxt) loadA2(k0 + 16);

        #pragma unroll
        for (int ks = 0; ks < 2; ks++) {
            int kb = ks * 8;
            uint32_t af[2][4], bf[4][2];
            #pragma unroll
            for (int mt = 0; mt < 2; mt++) {
                int mb = m0w + mt * 16 + g;
                af[mt][0] = As[buf][kb + t][mb];
                af[mt][1] = As[buf][kb + t][mb + 8];
                af[mt][2] = As[buf][kb + t + 4][mb];
                af[mt][3] = As[buf][kb + t + 4][mb + 8];
            }
            #pragma unroll
            for (int nt = 0; nt < 4; nt++) {
                int nb = n0w + nt * 8 + g;
                bf[nt][0] = hs[k0 + kb + t][nb];
                bf[nt][1] = hs[k0 + kb + t + 4][nb];
            }
            #pragma unroll
            for (int mt = 0; mt < 2; mt++)
                #pragma unroll
                for (int nt = 0; nt < 4; nt++)
                    mma_tf32(acc[mt][nt][0], acc[mt][nt][1], acc[mt][nt][2], acc[mt][nt][3],
                             af[mt][0], af[mt][1], af[mt][2], af[mt][3],
                             bf[nt][0], bf[nt][1]);
        }

        if (nxt) {
            writeS2(buf ^ 1);
            __syncthreads();
            buf ^= 1;
        }
    }

    #pragma unroll
    for (int mt = 0; mt < 2; mt++) {
        int gm = m0w + mt * 16 + g;
        #pragma unroll
        for (int nt = 0; nt < 4; nt++) {
            int gn = n0 + n0w + nt * 8 + 2 * t;
            if (gn < P) {
                Co[(size_t)gm * P + gn]       = acc[mt][nt][0];
                Co[(size_t)(gm + 8) * P + gn] = acc[mt][nt][2];
            }
            if (gn + 1 < P) {
                Co[(size_t)gm * P + gn + 1]       = acc[mt][nt][1];
                Co[(size_t)(gm + 8) * P + gn + 1] = acc[mt][nt][3];
            }
        }
    }
}

// small epilogue: add b_o to out
__global__ void addbias_k(float* __restrict__ outp, const float* __restrict__ bo)
{
    size_t i = (size_t)blockIdx.x * 256 + threadIdx.x;
    if (i < (size_t)NB * C * P) {
        int m = (i / P) % C;
        outp[i] += bo[m];
    }
}

// ============================================================
// gemm_big: exp-scores + row sums. tf32 MMA, BK=16.
// ============================================================
__global__ void __launch_bounds__(256) gemm_big_k(
    const uint32_t* __restrict__ Aq,
    const uint32_t* __restrict__ Bk,
    uint32_t* __restrict__ Cs,
    float* __restrict__ rs)
{
    __shared__ uint32_t As[2][16][136];
    __shared__ uint32_t Bs[2][16][136];
    const uint32_t* Ab = Aq + (size_t)blockIdx.z * C * P;
    const uint32_t* Bb = Bk + (size_t)blockIdx.z * C * D;
    uint32_t* Cb = Cs + (size_t)blockIdx.z * (size_t)P * D;
    float* rsb = rs + (size_t)blockIdx.z * P;

    const int m0 = blockIdx.y * 128, n0 = blockIdx.x * 128;
    const int tid = threadIdx.x;
    const int kf = tid >> 5, e4 = (tid & 31) * 4;
    const int warp = tid >> 5, lane = tid & 31;
    const int g = lane >> 2, t = lane & 3;
    const int wm = warp & 3, wn = warp >> 2;
    const int m0w = wm * 32, n0w = wn * 64;

    float acc[2][8][4];
    #pragma unroll
    for (int i = 0; i < 2; i++)
        #pragma unroll
        for (int j = 0; j < 8; j++)
            #pragma unroll
            for (int r = 0; r < 4; r++) acc[i][j][r] = 0.f;

    uint4 ra0, ra1, rb0, rb1;
    auto ld4A = [&](int krow, uint4& r) {
        const uint32_t* src = Ab + (size_t)krow * P;
        int m = m0 + e4;
        if (m + 3 < P) r = *(const uint4*)(src + m);
        else {
            r.x = (m+0 < P) ? src[m+0] : 0u;
            r.y = (m+1 < P) ? src[m+1] : 0u;
            r.z = (m+2 < P) ? src[m+2] : 0u;
            r.w = (m+3 < P) ? src[m+3] : 0u;
        }
    };
    auto ld4B = [&](int krow, uint4& r) {
        const uint32_t* src = Bb + (size_t)krow * D;
        int n = n0 + e4;
        if (n + 3 < D) r = *(const uint4*)(src + n);
        else {
            r.x = (n+0 < D) ? src[n+0] : 0u;
            r.y = (n+1 < D) ? src[n+1] : 0u;
            r.z = (n+2 < D) ? src[n+2] : 0u;
            r.w = (n+3 < D) ? src[n+3] : 0u;
        }
    };
    auto loadReg = [&](int k0) {
        ld4A(k0 + kf, ra0);
        ld4A(k0 + kf + 8, ra1);
        ld4B(k0 + kf, rb0);
        ld4B(k0 + kf + 8, rb1);
    };
    auto writeS = [&](int buf) {
        *(uint4*)&As[buf][kf][e4]   = ra0;
        *(uint4*)&As[buf][kf+8][e4] = ra1;
        *(uint4*)&Bs[buf][kf][e4]   = rb0;
        *(uint4*)&Bs[buf][kf+8][e4] = rb1;
    };

    loadReg(0);
    writeS(0);
    __syncthreads();

    int buf = 0;
    for (int k0 = 0; k0 < C; k0 += 16) {
        bool nxt = (k0 + 16) < C;
        if (nxt) loadReg(k0 + 16);

        #pragma unroll
        for (int ks = 0; ks < 2; ks++) {
            int kb = ks * 8;
            uint32_t af[2][4], bf[8][2];
            #pragma unroll
            for (int mt = 0; mt < 2; mt++) {
                int mb = m0w + mt * 16 + g;
                af[mt][0] = As[buf][kb + t][mb];
                af[mt][1] = As[buf][kb + t][mb + 8];
                af[mt][2] = As[buf][kb + t + 4][mb];
                af[mt][3] = As[buf][kb + t + 4][mb + 8];
            }
            #pragma unroll
            for (int nt = 0; nt < 8; nt++) {
                int nb = n0w + nt * 8 + g;
                bf[nt][0] = Bs[buf][kb + t][nb];
                bf[nt][1] = Bs[buf][kb + t + 4][nb];
            }
            #pragma unroll
            for (int mt = 0; mt < 2; mt++)
                #pragma unroll
                for (int nt = 0; nt < 8; nt++)
                    mma_tf32(acc[mt][nt][0], acc[mt][nt][1], acc[mt][nt][2], acc[mt][nt][3],
                             af[mt][0], af[mt][1], af[mt][2], af[mt][3],
                             bf[nt][0], bf[nt][1]);
        }

        if (nxt) {
            writeS(buf ^ 1);
            __syncthreads();
            buf ^= 1;
        }
    }

    #pragma unroll
    for (int mt = 0; mt < 2; mt++) {
        int gm = m0 + m0w + mt * 16 + g;
        float s0 = 0.f, s1 = 0.f;
        #pragma unroll
        for (int nt = 0; nt < 8; nt++) {
            int gn = n0 + n0w + nt * 8 + 2 * t;
            bool c0 = (gn < D), c1 = (gn + 1 < D);
            float e0 = __expf(acc[mt][nt][0]);
            float e1 = __expf(acc[mt][nt][1]);
            float e2 = __expf(acc[mt][nt][2]);
            float e3 = __expf(acc[mt][nt][3]);
            if (gm < P) {
                if (c0) Cb[(size_t)gm * D + gn]     = f2tf32(e0);
                if (c1) Cb[(size_t)gm * D + gn + 1] = f2tf32(e1);
            }
            if (gm + 8 < P) {
                if (c0) Cb[(size_t)(gm + 8) * D + gn]     = f2tf32(e2);
                if (c1) Cb[(size_t)(gm + 8) * D + gn + 1] = f2tf32(e3);
            }
            s0 += (c0 ? e0 : 0.f) + (c1 ? e1 : 0.f);
            s1 += (c0 ? e2 : 0.f) + (c1 ? e3 : 0.f);
        }
        s0 += __shfl_xor_sync(0xffffffff, s0, 1);
        s0 += __shfl_xor_sync(0xffffffff, s0, 2);
        s1 += __shfl_xor_sync(0xffffffff, s1, 1);
        s1 += __shfl_xor_sync(0xffffffff, s1, 2);
        if (t == 0) {
            if (gm < P)     atomicAdd(&rsb[gm], s0);
            if (gm + 8 < P) atomicAdd(&rsb[gm + 8], s1);
        }
    }
}

// -------- beff = b_h + W_h[:,2C:3C] @ v_c; v_c from constant c0 --------
__global__ void beff_k(const float* __restrict__ w_vc, const float* __restrict__ c0,
                       const float* __restrict__ w_h, const float* __restrict__ b_h,
                       float* __restrict__ beff)
{
    __shared__ float vc[C];
    int c = threadIdx.x;
    float s = 0.f;
    for (int ci = 0; ci < C; ci++) {
        float ws = 0.f;
        #pragma unroll
        for (int t = 0; t < 9; t++) ws += w_vc[((size_t)c * C + ci) * 9 + t];
        s += ws * c0[ci];
    }
    vc[c] = s;
    __syncthreads();
    float r = b_h[c];
    for (int j = 0; j < C; j++) r += w_h[(size_t)c * (3*C) + 2*C + j] * vc[j];
    beff[c] = r;
}

extern "C" void kernel_launch(void* const* d_in, const int* in_sizes, int n_in,
                              void* d_out, int out_size)
{
    const float* inp  = (const float*)d_in[0];
    const float* c0   = (const float*)d_in[1];
    const float* w_x  = (const float*)d_in[2];
    const float* b_x  = (const float*)d_in[3];
    const float* w_qx = (const float*)d_in[4];
    const float* w_kx = (const float*)d_in[6];
    const float* w_vx = (const float*)d_in[8];
    const float* w_vc = (const float*)d_in[9];
    const float* w_h  = (const float*)d_in[14];
    const float* b_h  = (const float*)d_in[15];
    const float* w_o  = (const float*)d_in[16];
    const float* b_o  = (const float*)d_in[17];
    float* out = (float*)d_out;

    uint32_t *xa, *q, *k, *v, *sc;
    float *rs, *beff;
    cudaGetSymbolAddress((void**)&xa,   g_xa);
    cudaGetSymbolAddress((void**)&q,    g_q);
    cudaGetSymbolAddress((void**)&k,    g_k);
    cudaGetSymbolAddress((void**)&v,    g_v);
    cudaGetSymbolAddress((void**)&sc,   g_sc);
    cudaGetSymbolAddress((void**)&rs,   g_rs);
    cudaGetSymbolAddress((void**)&beff, g_beff);
    uint32_t *wx;
    cudaGetSymbolAddress((void**)&wx, g_wx);

    const int NT_P = (P + 63) / 64;      // 21

    // constants and merged weight pre-conversion
    beff_k<<<1, C>>>(w_vc, c0, w_h, b_h, beff);
    preconv_all_k<<<(KC*C + 255)/256, 256>>>(w_x, w_h, w_o, w_qx, w_kx, w_vx);

    // x = W_x @ inp + b_x -> g_xa rows [0,128) as tf32 bits
    gemm64t_k<0,1,false,true><<<dim3(NT_P, 2, NB), 128>>>(
        wx, 0, C, inp, (size_t)C*P, P, xa, (size_t)2*C*P, P, P, C, b_x, 0);

    // q/k/v 3x3 convs, tf32 MMA mega-launch (cp.async loaders)
    qkv_mega_k<<<dim3(62, 1, NB), 128>>>(xa, q, k, v);

    // ex[p,d] = exp(q^T k) + row sums (fused)
    gemm_big_k<<<dim3((D + 127)/128, (P + 127)/128, NB), 256>>>(q, k, sc, rs);

    // a0[c,p] = (v @ ex^T)[c,p] / rs[p]
    gemm64t_k<1,3,true,true><<<dim3(NT_P, 2, NB), 128>>>(
        v, (size_t)C*D, D, sc, (size_t)P*D, D, xa + (size_t)C*P, (size_t)2*C*P, P,
        P, D, rs, P);

    // out = Wo @ tanh(Wh @ [x;a0] + beff)   (fused, b_o added after)
    hout_k<<<dim3(NT_P, 1, NB), 256>>>(xa, out);
    addbias_k<<<((size_t)NB*C*P + 255)/256, 256>>>(out, b_o);
}